// round 1
// baseline (speedup 1.0000x reference)
#include <cuda_runtime.h>
#include <cuda_bf16.h>
#include <cstdint>

#define N_USER 100000
#define N_SPOT 100000
#define F_IN   64
#define HID    128
#define OUTC   64
#define EDG    500000
#define LEAK   0.2f
#define EPSF   1e-6f

// ---------------------------------------------------------------------------
// Scratch (device globals; no allocation allowed)
// ---------------------------------------------------------------------------
__device__ float g_srcA[(size_t)N_USER * HID];   // src side of us-conv (and reuse layer1)
__device__ float g_tgtA[(size_t)N_SPOT * HID];   // tgt side of us-conv
__device__ float g_srcB[(size_t)N_SPOT * HID];   // src side of su-conv
__device__ float g_tgtB[(size_t)N_USER * HID];   // tgt side of su-conv
__device__ float g_hu[(size_t)N_USER * HID];     // layer0 user hidden (post relu)
__device__ float g_hs[(size_t)N_SPOT * HID];     // layer0 spot hidden (post relu)

__device__ float g_alsA[N_USER];  // alpha_src for us
__device__ float g_altA[N_SPOT];  // alpha_tgt for us
__device__ float g_alsB[N_SPOT];  // alpha_src for su
__device__ float g_altB[N_USER];  // alpha_tgt for su

__device__ int g_si2_us[EDG];
__device__ int g_si2_su[EDG];
__device__ int g_cnt_us[N_SPOT + 1];
__device__ int g_off_us[N_SPOT + 1];
__device__ int g_cur_us[N_SPOT + 1];
__device__ int g_cnt_su[N_USER + 1];
__device__ int g_off_su[N_USER + 1];
__device__ int g_cur_su[N_USER + 1];
__device__ int g_csr_us[EDG];   // s2 values in CSR-by-target order
__device__ int g_csr_su[EDG];

// ---------------------------------------------------------------------------
// Edge prep kernels
// ---------------------------------------------------------------------------
__global__ void k_gather2(const int* __restrict__ si, int* __restrict__ s2, int E) {
    int e = blockIdx.x * blockDim.x + threadIdx.x;
    if (e < E) {
        int a = si[e];          // in [0, N) < E, valid index into si
        s2[e] = si[a];          // faithful to src[si][si]
    }
}

__global__ void k_hist(const int* __restrict__ ti, int* __restrict__ cnt, int E) {
    int e = blockIdx.x * blockDim.x + threadIdx.x;
    if (e < E) atomicAdd(&cnt[ti[e]], 1);
}

// single-block exclusive scan over n counts -> off[0..n], cur copy
__global__ void k_scan(const int* __restrict__ cnt, int* __restrict__ off,
                       int* __restrict__ cur, int n) {
    __shared__ int s[1024];
    int tid = threadIdx.x;
    int chunk = (n + 1023) / 1024;
    int beg = tid * chunk;
    int end = beg + chunk; if (end > n) end = n; if (beg > n) beg = n;
    int sum = 0;
    for (int i = beg; i < end; i++) sum += cnt[i];
    s[tid] = sum;
    __syncthreads();
    for (int d = 1; d < 1024; d <<= 1) {
        int v = 0;
        if (tid >= d) v = s[tid - d];
        __syncthreads();
        s[tid] += v;
        __syncthreads();
    }
    int run = s[tid] - sum;   // exclusive base
    for (int i = beg; i < end; i++) {
        off[i] = run; cur[i] = run;
        run += cnt[i];
    }
    if (tid == 1023) off[n] = s[1023];
}

__global__ void k_scatter(const int* __restrict__ ti, const int* __restrict__ s2,
                          int* __restrict__ cur, int* __restrict__ csr, int E) {
    int e = blockIdx.x * blockDim.x + threadIdx.x;
    if (e < E) {
        int p = atomicAdd(&cur[ti[e]], 1);
        csr[p] = s2[e];
    }
}

// ---------------------------------------------------------------------------
// GEMM: Y[M,BN] = X[M,K] @ W[K,BN]  (BN = 16*TN), optional fused
//   ALPHA: alphaOut[m] = dot(Y[m,:], avec[:BN])
//   BIAS : Y[m,n] += bias[n]
// BM=128 rows per block, 256 threads, thread tile TM x TN = 8 x TN.
// ---------------------------------------------------------------------------
template <int TN, bool ALPHA, bool BIAS>
__global__ __launch_bounds__(256)
void k_gemm(const float* __restrict__ X, const float* __restrict__ W,
            const float* __restrict__ avec, const float* __restrict__ bias,
            float* __restrict__ Y, float* __restrict__ alphaOut,
            int M, int K) {
    constexpr int BN = 16 * TN;
    constexpr int BM = 128;
    constexpr int BK = 32;
    constexpr int TM = 8;
    __shared__ float Xs[BK][BM];
    __shared__ float Wsm[BK][BN];

    int tid = threadIdx.x;
    int tx = tid & 15;
    int ty = tid >> 4;
    int rowBase = blockIdx.x * BM;

    float acc[TM][TN];
#pragma unroll
    for (int i = 0; i < TM; i++)
#pragma unroll
        for (int j = 0; j < TN; j++) acc[i][j] = 0.f;

    for (int k0 = 0; k0 < K; k0 += BK) {
        // load X tile [BM x BK] -> transposed smem
#pragma unroll
        for (int t = 0; t < 4; t++) {
            int fid = tid + t * 256;          // 0..1023 float4 ids
            int r = fid >> 3;
            int c4 = (fid & 7) << 2;
            int grow = rowBase + r;
            float4 v = make_float4(0.f, 0.f, 0.f, 0.f);
            if (grow < M) v = *(const float4*)(X + (size_t)grow * K + k0 + c4);
            Xs[c4 + 0][r] = v.x;
            Xs[c4 + 1][r] = v.y;
            Xs[c4 + 2][r] = v.z;
            Xs[c4 + 3][r] = v.w;
        }
        // load W tile [BK x BN]
        constexpr int WF = (BK * BN) / 4 / 256;   // 4 for BN=128, 2 for BN=64
#pragma unroll
        for (int t = 0; t < WF; t++) {
            int fid = tid + t * 256;
            int r = fid / (BN / 4);
            int c4 = (fid % (BN / 4)) << 2;
            *(float4*)&Wsm[r][c4] = *(const float4*)(W + (size_t)(k0 + r) * BN + c4);
        }
        __syncthreads();

#pragma unroll
        for (int k = 0; k < BK; k++) {
            float xv[TM], wv[TN];
#pragma unroll
            for (int i = 0; i < TM; i++) xv[i] = Xs[k][ty * TM + i];
#pragma unroll
            for (int j = 0; j < TN; j++) wv[j] = Wsm[k][tx * TN + j];
#pragma unroll
            for (int i = 0; i < TM; i++)
#pragma unroll
                for (int j = 0; j < TN; j++) acc[i][j] += xv[i] * wv[j];
        }
        __syncthreads();
    }

    // store
#pragma unroll
    for (int i = 0; i < TM; i++) {
        int grow = rowBase + ty * TM + i;
        if (grow < M) {
#pragma unroll
            for (int j = 0; j < TN; j += 4) {
                float4 v = make_float4(acc[i][j], acc[i][j + 1], acc[i][j + 2], acc[i][j + 3]);
                if (BIAS) {
                    int c = tx * TN + j;
                    v.x += bias[c]; v.y += bias[c + 1]; v.z += bias[c + 2]; v.w += bias[c + 3];
                }
                *(float4*)(Y + (size_t)grow * BN + tx * TN + j) = v;
            }
        }
    }

    if (ALPHA) {
#pragma unroll
        for (int i = 0; i < TM; i++) {
            float p = 0.f;
#pragma unroll
            for (int j = 0; j < TN; j++) p += acc[i][j] * avec[tx * TN + j];
            // reduce across the 16 tx lanes (xor masks < 16 stay inside each half-warp group)
            p += __shfl_xor_sync(0xffffffffu, p, 8);
            p += __shfl_xor_sync(0xffffffffu, p, 4);
            p += __shfl_xor_sync(0xffffffffu, p, 2);
            p += __shfl_xor_sync(0xffffffffu, p, 1);
            int grow = rowBase + ty * TM + i;
            if (tx == 0 && grow < M) alphaOut[grow] = p;
        }
    }
}

// ---------------------------------------------------------------------------
// Aggregation: one warp per target node.
//   out[t] = relu( tgt[t] + (sum_e att*src[s2]) / (sum_e att + eps) )
//   att = exp(leaky_relu(alpha_s[s2] + alpha_t[t]))
// ---------------------------------------------------------------------------
__global__ __launch_bounds__(256)
void k_agg(const float4* __restrict__ tgt, const float4* __restrict__ src,
           const float* __restrict__ alpha_s, const float* __restrict__ alpha_t,
           const int* __restrict__ off, const int* __restrict__ csr,
           float4* __restrict__ out, int n) {
    int w = (blockIdx.x * blockDim.x + threadIdx.x) >> 5;
    int lid = threadIdx.x & 31;
    if (w >= n) return;
    float at = alpha_t[w];
    int beg = off[w];
    int end = off[w + 1];
    float4 acc = make_float4(0.f, 0.f, 0.f, 0.f);
    float den = 0.f;
    for (int j = beg; j < end; j++) {
        int s2 = csr[j];
        float l = alpha_s[s2] + at;
        l = (l > 0.f) ? l : LEAK * l;
        float a = __expf(l);
        den += a;
        float4 v = src[(size_t)s2 * 32 + lid];
        acc.x += a * v.x; acc.y += a * v.y; acc.z += a * v.z; acc.w += a * v.w;
    }
    float inv = 1.0f / (den + EPSF);
    float4 t = tgt[(size_t)w * 32 + lid];
    float4 r;
    r.x = fmaxf(t.x + acc.x * inv, 0.f);
    r.y = fmaxf(t.y + acc.y * inv, 0.f);
    r.z = fmaxf(t.z + acc.z * inv, 0.f);
    r.w = fmaxf(t.w + acc.w * inv, 0.f);
    out[(size_t)w * 32 + lid] = r;
}

// ---------------------------------------------------------------------------
// Host launcher
// ---------------------------------------------------------------------------
static inline float* symf(const void* sym) {
    void* p = nullptr;
    cudaGetSymbolAddress(&p, sym);
    return (float*)p;
}
static inline int* symi(const void* sym) {
    void* p = nullptr;
    cudaGetSymbolAddress(&p, sym);
    return (int*)p;
}

extern "C" void kernel_launch(void* const* d_in, const int* in_sizes, int n_in,
                              void* d_out, int out_size) {
    const float* x_user = (const float*)d_in[0];
    const float* x_spot = (const float*)d_in[1];
    const int*   e_us   = (const int*)d_in[2];   // [2, E] row0=src(user) row1=tgt(spot)
    const int*   e_su   = (const int*)d_in[3];   // [2, E] row0=src(spot) row1=tgt(user)
    const float* Ws_us0 = (const float*)d_in[4];
    const float* Wt_us0 = (const float*)d_in[5];
    const float* a_us0  = (const float*)d_in[6];
    const float* Ws_su0 = (const float*)d_in[7];
    const float* Wt_su0 = (const float*)d_in[8];
    const float* a_su0  = (const float*)d_in[9];
    const float* Ws_us1 = (const float*)d_in[10];
    const float* Wt_us1 = (const float*)d_in[11];
    const float* a_us1  = (const float*)d_in[12];
    const float* Ws_su1 = (const float*)d_in[13];
    const float* Wt_su1 = (const float*)d_in[14];
    const float* a_su1  = (const float*)d_in[15];
    const float* W_ou   = (const float*)d_in[16];
    const float* b_ou   = (const float*)d_in[17];
    const float* W_os   = (const float*)d_in[18];
    const float* b_os   = (const float*)d_in[19];

    float* out = (float*)d_out;
    float* xu_out = out;                                   // [N_USER,128]
    float* xs_out = out + (size_t)N_USER * HID;            // [N_SPOT,128]
    float* ou_out = xs_out + (size_t)N_SPOT * HID;         // [N_USER,64]
    float* os_out = ou_out + (size_t)N_USER * OUTC;        // [N_SPOT,64]

    float* srcA = symf(g_srcA); float* tgtA = symf(g_tgtA);
    float* srcB = symf(g_srcB); float* tgtB = symf(g_tgtB);
    float* hu = symf(g_hu);     float* hs = symf(g_hs);
    float* alsA = symf(g_alsA); float* altA = symf(g_altA);
    float* alsB = symf(g_alsB); float* altB = symf(g_altB);
    int* si2_us = symi(g_si2_us); int* si2_su = symi(g_si2_su);
    int* cnt_us = symi(g_cnt_us); int* off_us = symi(g_off_us); int* cur_us = symi(g_cur_us);
    int* cnt_su = symi(g_cnt_su); int* off_su = symi(g_off_su); int* cur_su = symi(g_cur_su);
    int* csr_us = symi(g_csr_us); int* csr_su = symi(g_csr_su);

    const int EB = (EDG + 255) / 256;
    const int GU = (N_USER + 127) / 128;   // gemm blocks (M rows)
    const int GS = (N_SPOT + 127) / 128;
    const int AU = (N_USER * 32 + 255) / 256;  // agg: warp per node, 8 warps/block
    const int AS = (N_SPOT * 32 + 255) / 256;

    // ---- edge prep (shared by both layers) ----
    k_gather2<<<EB, 256>>>(e_us, si2_us, EDG);
    k_gather2<<<EB, 256>>>(e_su, si2_su, EDG);
    cudaMemsetAsync(cnt_us, 0, sizeof(int) * (N_SPOT + 1));
    cudaMemsetAsync(cnt_su, 0, sizeof(int) * (N_USER + 1));
    k_hist<<<EB, 256>>>(e_us + EDG, cnt_us, EDG);
    k_hist<<<EB, 256>>>(e_su + EDG, cnt_su, EDG);
    k_scan<<<1, 1024>>>(cnt_us, off_us, cur_us, N_SPOT);
    k_scan<<<1, 1024>>>(cnt_su, off_su, cur_su, N_USER);
    k_scatter<<<EB, 256>>>(e_us + EDG, si2_us, cur_us, csr_us, EDG);
    k_scatter<<<EB, 256>>>(e_su + EDG, si2_su, cur_su, csr_su, EDG);

    // ---- layer 0 (K = 64) ----
    k_gemm<8, true, false><<<GU, 256>>>(x_user, Ws_us0, a_us0,        nullptr, srcA, alsA, N_USER, F_IN);
    k_gemm<8, true, false><<<GS, 256>>>(x_spot, Wt_us0, a_us0 + HID,  nullptr, tgtA, altA, N_SPOT, F_IN);
    k_gemm<8, true, false><<<GS, 256>>>(x_spot, Ws_su0, a_su0,        nullptr, srcB, alsB, N_SPOT, F_IN);
    k_gemm<8, true, false><<<GU, 256>>>(x_user, Wt_su0, a_su0 + HID,  nullptr, tgtB, altB, N_USER, F_IN);
    k_agg<<<AS, 256>>>((const float4*)tgtA, (const float4*)srcA, alsA, altA, off_us, csr_us, (float4*)hs, N_SPOT);
    k_agg<<<AU, 256>>>((const float4*)tgtB, (const float4*)srcB, alsB, altB, off_su, csr_su, (float4*)hu, N_USER);

    // ---- layer 1 (K = 128) ----
    k_gemm<8, true, false><<<GU, 256>>>(hu, Ws_us1, a_us1,        nullptr, srcA, alsA, N_USER, HID);
    k_gemm<8, true, false><<<GS, 256>>>(hs, Wt_us1, a_us1 + HID,  nullptr, tgtA, altA, N_SPOT, HID);
    k_gemm<8, true, false><<<GS, 256>>>(hs, Ws_su1, a_su1,        nullptr, srcB, alsB, N_SPOT, HID);
    k_gemm<8, true, false><<<GU, 256>>>(hu, Wt_su1, a_su1 + HID,  nullptr, tgtB, altB, N_USER, HID);
    k_agg<<<AS, 256>>>((const float4*)tgtA, (const float4*)srcA, alsA, altA, off_us, csr_us, (float4*)xs_out, N_SPOT);
    k_agg<<<AU, 256>>>((const float4*)tgtB, (const float4*)srcB, alsB, altB, off_su, csr_su, (float4*)xu_out, N_USER);

    // ---- final per-type linear (K = 128, N = 64, bias) ----
    k_gemm<4, false, true><<<GU, 256>>>(xu_out, W_ou, nullptr, b_ou, ou_out, nullptr, N_USER, HID);
    k_gemm<4, false, true><<<GS, 256>>>(xs_out, W_os, nullptr, b_os, os_out, nullptr, N_SPOT, HID);
}

// round 3
// speedup vs baseline: 1.0933x; 1.0933x over previous
#include <cuda_runtime.h>
#include <cuda_bf16.h>
#include <cstdint>

#define N_USER 100000
#define N_SPOT 100000
#define F_IN   64
#define HID    128
#define OUTC   64
#define EDG    500000
#define LEAK   0.2f
#define EPSF   1e-6f

// ---------------------------------------------------------------------------
// Scratch (device globals; no allocation allowed)
// ---------------------------------------------------------------------------
__device__ float g_srcA[(size_t)N_USER * HID];
__device__ float g_tgtA[(size_t)N_SPOT * HID];
__device__ float g_srcB[(size_t)N_SPOT * HID];
__device__ float g_tgtB[(size_t)N_USER * HID];
__device__ float g_hu[(size_t)N_USER * HID];
__device__ float g_hs[(size_t)N_SPOT * HID];

__device__ float g_alsA[N_USER];
__device__ float g_altA[N_SPOT];
__device__ float g_alsB[N_SPOT];
__device__ float g_altB[N_USER];

__device__ int g_si2_us[EDG];
__device__ int g_si2_su[EDG];
__device__ int g_cnt_us[N_SPOT + 1];
__device__ int g_off_us[N_SPOT + 1];
__device__ int g_cur_us[N_SPOT + 1];
__device__ int g_cnt_su[N_USER + 1];
__device__ int g_off_su[N_USER + 1];
__device__ int g_cur_su[N_USER + 1];
__device__ int g_csr_us[EDG];
__device__ int g_csr_su[EDG];

__device__ __forceinline__ float f2tf32(float x) {
    float y;
    asm("cvt.rna.tf32.f32 %0, %1;" : "=f"(y) : "f"(x));
    return y;
}

// ---------------------------------------------------------------------------
// Edge prep kernels
// ---------------------------------------------------------------------------
__global__ void k_gather2(const int* __restrict__ si, int* __restrict__ s2, int E) {
    int e = blockIdx.x * blockDim.x + threadIdx.x;
    if (e < E) {
        int a = si[e];
        s2[e] = si[a];
    }
}

__global__ void k_hist(const int* __restrict__ ti, int* __restrict__ cnt, int E) {
    int e = blockIdx.x * blockDim.x + threadIdx.x;
    if (e < E) atomicAdd(&cnt[ti[e]], 1);
}

__global__ void k_scan(const int* __restrict__ cnt, int* __restrict__ off,
                       int* __restrict__ cur, int n) {
    __shared__ int s[1024];
    int tid = threadIdx.x;
    int chunk = (n + 1023) / 1024;
    int beg = tid * chunk;
    int end = beg + chunk; if (end > n) end = n; if (beg > n) beg = n;
    int sum = 0;
    for (int i = beg; i < end; i++) sum += cnt[i];
    s[tid] = sum;
    __syncthreads();
    for (int d = 1; d < 1024; d <<= 1) {
        int v = 0;
        if (tid >= d) v = s[tid - d];
        __syncthreads();
        s[tid] += v;
        __syncthreads();
    }
    int run = s[tid] - sum;
    for (int i = beg; i < end; i++) {
        off[i] = run; cur[i] = run;
        run += cnt[i];
    }
    if (tid == 1023) off[n] = s[1023];
}

__global__ void k_scatter(const int* __restrict__ ti, const int* __restrict__ s2,
                          int* __restrict__ cur, int* __restrict__ csr, int E) {
    int e = blockIdx.x * blockDim.x + threadIdx.x;
    if (e < E) {
        int p = atomicAdd(&cur[ti[e]], 1);
        csr[p] = s2[e];
    }
}

// ---------------------------------------------------------------------------
// tf32 mma.sync GEMM: Y[M,BN] = X[M,K] @ W[K,BN]
// BM=128, 256 threads (8 warps, 4x2), warp tile 32 x (BN/2).
// Whole-K staged in smem (K <= 128). Optional fused alpha dot / bias.
// ---------------------------------------------------------------------------
template <int K, int BN, bool ALPHA, bool BIAS>
__global__ __launch_bounds__(256)
void k_gemm_tc(const float* __restrict__ X, const float* __restrict__ W,
               const float* __restrict__ avec, const float* __restrict__ bias,
               float* __restrict__ Y, float* __restrict__ alphaOut, int M) {
    constexpr int BM = 128;
    constexpr int KP = K + 4;          // padded row stride (floats)
    constexpr int WN = BN / 2;         // warp tile N
    constexpr int NT = WN / 8;         // n8 tiles per warp
    extern __shared__ float smf[];
    float* As = smf;                   // [BM][KP]
    float* Bs = smf + BM * KP;         // [BN][KP]  (n-major, k contiguous)

    const int tid = threadIdx.x;
    const int wid = tid >> 5;
    const int lane = tid & 31;
    const int warpM = wid >> 1;        // 0..3
    const int warpN = wid & 1;         // 0..1
    const int rowBase = blockIdx.x * BM;

    // ---- stage X tile [BM x K] ----
    for (int i = tid; i < BM * K / 4; i += 256) {
        int r = i / (K / 4);
        int c4 = (i % (K / 4)) * 4;
        float4 v = make_float4(0.f, 0.f, 0.f, 0.f);
        int gr = rowBase + r;
        if (gr < M) v = *(const float4*)(X + (size_t)gr * K + c4);
        v.x = f2tf32(v.x); v.y = f2tf32(v.y); v.z = f2tf32(v.z); v.w = f2tf32(v.w);
        *(float4*)(As + r * KP + c4) = v;
    }
    // ---- stage W [K x BN] transposed -> Bs[n][k] ----
    for (int i = tid; i < K * BN / 4; i += 256) {
        int k = i / (BN / 4);
        int n4 = (i % (BN / 4)) * 4;
        float4 v = *(const float4*)(W + (size_t)k * BN + n4);
        Bs[(n4 + 0) * KP + k] = f2tf32(v.x);
        Bs[(n4 + 1) * KP + k] = f2tf32(v.y);
        Bs[(n4 + 2) * KP + k] = f2tf32(v.z);
        Bs[(n4 + 3) * KP + k] = f2tf32(v.w);
    }
    __syncthreads();

    // ---- MMA mainloop ----
    float acc[2][NT][4];
#pragma unroll
    for (int mt = 0; mt < 2; mt++)
#pragma unroll
        for (int nt = 0; nt < NT; nt++)
#pragma unroll
            for (int j = 0; j < 4; j++) acc[mt][nt][j] = 0.f;

    const int q = lane >> 2;       // 0..7
    const int t = lane & 3;        // 0..3
    const uint32_t* Au = (const uint32_t*)As;
    const uint32_t* Bu = (const uint32_t*)Bs;

#pragma unroll
    for (int kk = 0; kk < K; kk += 8) {
        uint32_t a[2][4];
#pragma unroll
        for (int mt = 0; mt < 2; mt++) {
            int r0 = warpM * 32 + mt * 16 + q;
            a[mt][0] = Au[r0 * KP + kk + t];
            a[mt][1] = Au[(r0 + 8) * KP + kk + t];
            a[mt][2] = Au[r0 * KP + kk + 4 + t];
            a[mt][3] = Au[(r0 + 8) * KP + kk + 4 + t];
        }
        uint32_t b[NT][2];
#pragma unroll
        for (int nt = 0; nt < NT; nt++) {
            int nc = warpN * WN + nt * 8 + q;
            b[nt][0] = Bu[nc * KP + kk + t];
            b[nt][1] = Bu[nc * KP + kk + 4 + t];
        }
#pragma unroll
        for (int mt = 0; mt < 2; mt++)
#pragma unroll
            for (int nt = 0; nt < NT; nt++) {
                asm("mma.sync.aligned.m16n8k8.row.col.f32.tf32.tf32.f32 "
                    "{%0,%1,%2,%3}, {%4,%5,%6,%7}, {%8,%9}, {%0,%1,%2,%3};"
                    : "+f"(acc[mt][nt][0]), "+f"(acc[mt][nt][1]),
                      "+f"(acc[mt][nt][2]), "+f"(acc[mt][nt][3])
                    : "r"(a[mt][0]), "r"(a[mt][1]), "r"(a[mt][2]), "r"(a[mt][3]),
                      "r"(b[nt][0]), "r"(b[nt][1]));
            }
    }

    // ---- epilogue ----
#pragma unroll
    for (int mt = 0; mt < 2; mt++) {
        int r0 = rowBase + warpM * 32 + mt * 16 + q;   // and r0+8
        float p0 = 0.f, p1 = 0.f;
#pragma unroll
        for (int nt = 0; nt < NT; nt++) {
            int cb = warpN * WN + nt * 8 + t * 2;
            float v0 = acc[mt][nt][0], v1 = acc[mt][nt][1];
            float v2 = acc[mt][nt][2], v3 = acc[mt][nt][3];
            if (BIAS) {
                v0 += bias[cb]; v1 += bias[cb + 1];
                v2 += bias[cb]; v3 += bias[cb + 1];
            }
            if (r0 < M) *(float2*)(Y + (size_t)r0 * BN + cb) = make_float2(v0, v1);
            if (r0 + 8 < M) *(float2*)(Y + (size_t)(r0 + 8) * BN + cb) = make_float2(v2, v3);
            if (ALPHA) {
                p0 += v0 * avec[cb] + v1 * avec[cb + 1];
                p1 += v2 * avec[cb] + v3 * avec[cb + 1];
            }
        }
        if (ALPHA) {
            // reduce over the 4 lanes of the quad (t = lane&3) AND the two
            // warpN halves: lanes t(0..3) ^ warpN-partner.  warpN partner is in
            // a different warp -> use smem-free trick: atomic-free via two-step:
            // reduce within quad, then add the other warp's half via global?
            // Simpler: each warpN half covers distinct columns; reduce quad,
            // then atomicAdd into alphaOut (initialized by warpN==0 store).
            p0 += __shfl_xor_sync(0xffffffffu, p0, 1);
            p0 += __shfl_xor_sync(0xffffffffu, p0, 2);
            p1 += __shfl_xor_sync(0xffffffffu, p1, 1);
            p1 += __shfl_xor_sync(0xffffffffu, p1, 2);
            if (t == 0) {
                if (warpN == 0) {
                    if (r0 < M) alphaOut[r0] = p0;
                    if (r0 + 8 < M) alphaOut[r0 + 8] = p1;
                }
            }
        }
    }
    if (ALPHA) {
        __syncthreads();   // warpN==0 stores visible before warpN==1 adds
#pragma unroll
        for (int mt = 0; mt < 2; mt++) {
            int r0 = rowBase + warpM * 32 + mt * 16 + q;
            float p0 = 0.f, p1 = 0.f;
#pragma unroll
            for (int nt = 0; nt < NT; nt++) {
                int cb = warpN * WN + nt * 8 + t * 2;
                p0 += acc[mt][nt][0] * avec[cb] + acc[mt][nt][1] * avec[cb + 1];
                p1 += acc[mt][nt][2] * avec[cb] + acc[mt][nt][3] * avec[cb + 1];
            }
            p0 += __shfl_xor_sync(0xffffffffu, p0, 1);
            p0 += __shfl_xor_sync(0xffffffffu, p0, 2);
            p1 += __shfl_xor_sync(0xffffffffu, p1, 1);
            p1 += __shfl_xor_sync(0xffffffffu, p1, 2);
            if (t == 0 && warpN == 1) {
                if (r0 < M) atomicAdd(&alphaOut[r0], p0);
                if (r0 + 8 < M) atomicAdd(&alphaOut[r0 + 8], p1);
            }
        }
    }
}

// ---------------------------------------------------------------------------
// Aggregation: one warp per target node.
// ---------------------------------------------------------------------------
__global__ __launch_bounds__(256)
void k_agg(const float4* __restrict__ tgt, const float4* __restrict__ src,
           const float* __restrict__ alpha_s, const float* __restrict__ alpha_t,
           const int* __restrict__ off, const int* __restrict__ csr,
           float4* __restrict__ out, int n) {
    int w = (blockIdx.x * blockDim.x + threadIdx.x) >> 5;
    int lid = threadIdx.x & 31;
    if (w >= n) return;
    float at = alpha_t[w];
    int beg = off[w];
    int end = off[w + 1];
    float4 acc = make_float4(0.f, 0.f, 0.f, 0.f);
    float den = 0.f;
    for (int j = beg; j < end; j++) {
        int s2 = csr[j];
        float l = alpha_s[s2] + at;
        l = (l > 0.f) ? l : LEAK * l;
        float a = __expf(l);
        den += a;
        float4 v = src[(size_t)s2 * 32 + lid];
        acc.x += a * v.x; acc.y += a * v.y; acc.z += a * v.z; acc.w += a * v.w;
    }
    float inv = 1.0f / (den + EPSF);
    float4 t = tgt[(size_t)w * 32 + lid];
    float4 r;
    r.x = fmaxf(t.x + acc.x * inv, 0.f);
    r.y = fmaxf(t.y + acc.y * inv, 0.f);
    r.z = fmaxf(t.z + acc.z * inv, 0.f);
    r.w = fmaxf(t.w + acc.w * inv, 0.f);
    out[(size_t)w * 32 + lid] = r;
}

// ---------------------------------------------------------------------------
// Host launcher
// ---------------------------------------------------------------------------
static inline float* symf(const void* sym) {
    void* p = nullptr;
    cudaGetSymbolAddress(&p, sym);
    return (float*)p;
}
static inline int* symi(const void* sym) {
    void* p = nullptr;
    cudaGetSymbolAddress(&p, sym);
    return (int*)p;
}

extern "C" void kernel_launch(void* const* d_in, const int* in_sizes, int n_in,
                              void* d_out, int out_size) {
    const float* x_user = (const float*)d_in[0];
    const float* x_spot = (const float*)d_in[1];
    const int*   e_us   = (const int*)d_in[2];
    const int*   e_su   = (const int*)d_in[3];
    const float* Ws_us0 = (const float*)d_in[4];
    const float* Wt_us0 = (const float*)d_in[5];
    const float* a_us0  = (const float*)d_in[6];
    const float* Ws_su0 = (const float*)d_in[7];
    const float* Wt_su0 = (const float*)d_in[8];
    const float* a_su0  = (const float*)d_in[9];
    const float* Ws_us1 = (const float*)d_in[10];
    const float* Wt_us1 = (const float*)d_in[11];
    const float* a_us1  = (const float*)d_in[12];
    const float* Ws_su1 = (const float*)d_in[13];
    const float* Wt_su1 = (const float*)d_in[14];
    const float* a_su1  = (const float*)d_in[15];
    const float* W_ou   = (const float*)d_in[16];
    const float* b_ou   = (const float*)d_in[17];
    const float* W_os   = (const float*)d_in[18];
    const float* b_os   = (const float*)d_in[19];

    float* out = (float*)d_out;
    float* xu_out = out;
    float* xs_out = out + (size_t)N_USER * HID;
    float* ou_out = xs_out + (size_t)N_SPOT * HID;
    float* os_out = ou_out + (size_t)N_USER * OUTC;

    float* srcA = symf(g_srcA); float* tgtA = symf(g_tgtA);
    float* srcB = symf(g_srcB); float* tgtB = symf(g_tgtB);
    float* hu = symf(g_hu);     float* hs = symf(g_hs);
    float* alsA = symf(g_alsA); float* altA = symf(g_altA);
    float* alsB = symf(g_alsB); float* altB = symf(g_altB);
    int* si2_us = symi(g_si2_us); int* si2_su = symi(g_si2_su);
    int* cnt_us = symi(g_cnt_us); int* off_us = symi(g_off_us); int* cur_us = symi(g_cur_us);
    int* cnt_su = symi(g_cnt_su); int* off_su = symi(g_off_su); int* cur_su = symi(g_cur_su);
    int* csr_us = symi(g_csr_us); int* csr_su = symi(g_csr_su);

    const int EB = (EDG + 255) / 256;
    const int G = (N_USER + 127) / 128;
    const int AU = (N_USER * 32 + 255) / 256;
    const int AS = (N_SPOT * 32 + 255) / 256;

    const int SM_L0 = (128 * (64 + 4) + 128 * (64 + 4)) * 4;     // 69.6 KB
    const int SM_L1 = (128 * (128 + 4) + 128 * (128 + 4)) * 4;   // 135 KB
    const int SM_FN = (128 * (128 + 4) + 64 * (128 + 4)) * 4;    // 101 KB

    cudaFuncSetAttribute((const void*)k_gemm_tc<64, 128, true, false>,
                         cudaFuncAttributeMaxDynamicSharedMemorySize, SM_L0);
    cudaFuncSetAttribute((const void*)k_gemm_tc<128, 128, true, false>,
                         cudaFuncAttributeMaxDynamicSharedMemorySize, SM_L1);
    cudaFuncSetAttribute((const void*)k_gemm_tc<128, 64, false, true>,
                         cudaFuncAttributeMaxDynamicSharedMemorySize, SM_FN);

    // ---- edge prep ----
    k_gather2<<<EB, 256>>>(e_us, si2_us, EDG);
    k_gather2<<<EB, 256>>>(e_su, si2_su, EDG);
    cudaMemsetAsync(cnt_us, 0, sizeof(int) * (N_SPOT + 1));
    cudaMemsetAsync(cnt_su, 0, sizeof(int) * (N_USER + 1));
    k_hist<<<EB, 256>>>(e_us + EDG, cnt_us, EDG);
    k_hist<<<EB, 256>>>(e_su + EDG, cnt_su, EDG);
    k_scan<<<1, 1024>>>(cnt_us, off_us, cur_us, N_SPOT);
    k_scan<<<1, 1024>>>(cnt_su, off_su, cur_su, N_USER);
    k_scatter<<<EB, 256>>>(e_us + EDG, si2_us, cur_us, csr_us, EDG);
    k_scatter<<<EB, 256>>>(e_su + EDG, si2_su, cur_su, csr_su, EDG);

    // ---- layer 0 (K=64) ----
    k_gemm_tc<64, 128, true, false><<<G, 256, SM_L0>>>(x_user, Ws_us0, a_us0,       nullptr, srcA, alsA, N_USER);
    k_gemm_tc<64, 128, true, false><<<G, 256, SM_L0>>>(x_spot, Wt_us0, a_us0 + HID, nullptr, tgtA, altA, N_SPOT);
    k_gemm_tc<64, 128, true, false><<<G, 256, SM_L0>>>(x_spot, Ws_su0, a_su0,       nullptr, srcB, alsB, N_SPOT);
    k_gemm_tc<64, 128, true, false><<<G, 256, SM_L0>>>(x_user, Wt_su0, a_su0 + HID, nullptr, tgtB, altB, N_USER);
    k_agg<<<AS, 256>>>((const float4*)tgtA, (const float4*)srcA, alsA, altA,
                       off_us, csr_us, (float4*)hs, N_SPOT);
    k_agg<<<AU, 256>>>((const float4*)tgtB, (const float4*)srcB, alsB, altB,
                       off_su, csr_su, (float4*)hu, N_USER);

    // ---- layer 1 (K=128) ----
    k_gemm_tc<128, 128, true, false><<<G, 256, SM_L1>>>(hu, Ws_us1, a_us1,       nullptr, srcA, alsA, N_USER);
    k_gemm_tc<128, 128, true, false><<<G, 256, SM_L1>>>(hs, Wt_us1, a_us1 + HID, nullptr, tgtA, altA, N_SPOT);
    k_gemm_tc<128, 128, true, false><<<G, 256, SM_L1>>>(hs, Ws_su1, a_su1,       nullptr, srcB, alsB, N_SPOT);
    k_gemm_tc<128, 128, true, false><<<G, 256, SM_L1>>>(hu, Wt_su1, a_su1 + HID, nullptr, tgtB, altB, N_USER);
    k_agg<<<AS, 256>>>((const float4*)tgtA, (const float4*)srcA, alsA, altA,
                       off_us, csr_us, (float4*)xs_out, N_SPOT);
    k_agg<<<AU, 256>>>((const float4*)tgtB, (const float4*)srcB, alsB, altB,
                       off_su, csr_su, (float4*)xu_out, N_USER);

    // ---- final per-type linear (K=128, N=64, bias) ----
    k_gemm_tc<128, 64, false, true><<<G, 256, SM_FN>>>(xu_out, W_ou, nullptr, b_ou, ou_out, nullptr, N_USER);
    k_gemm_tc<128, 64, false, true><<<G, 256, SM_FN>>>(xs_out, W_os, nullptr, b_os, os_out, nullptr, N_SPOT);
}

// round 5
// speedup vs baseline: 1.2872x; 1.1773x over previous
#include <cuda_runtime.h>
#include <cuda_bf16.h>
#include <cstdint>

#define N_USER 100000
#define N_SPOT 100000
#define F_IN   64
#define HID    128
#define OUTC   64
#define EDG    500000
#define LEAK   0.2f
#define EPSF   1e-6f

// ---------------------------------------------------------------------------
// Scratch (device globals; no allocation allowed)
// ---------------------------------------------------------------------------
__device__ float g_srcA[(size_t)N_USER * HID];
__device__ float g_tgtA[(size_t)N_SPOT * HID];
__device__ float g_srcB[(size_t)N_SPOT * HID];
__device__ float g_tgtB[(size_t)N_USER * HID];
__device__ float g_hu[(size_t)N_USER * HID];
__device__ float g_hs[(size_t)N_SPOT * HID];

__device__ float g_alsA[N_USER];
__device__ float g_altA[N_SPOT];
__device__ float g_alsB[N_SPOT];
__device__ float g_altB[N_USER];

__device__ int g_si2_us[EDG];
__device__ int g_si2_su[EDG];
__device__ int g_cnt_us[N_SPOT + 1];
__device__ int g_off_us[N_SPOT + 1];
__device__ int g_cur_us[N_SPOT + 1];
__device__ int g_cnt_su[N_USER + 1];
__device__ int g_off_su[N_USER + 1];
__device__ int g_cur_su[N_USER + 1];
__device__ int g_csr_us[EDG];
__device__ int g_csr_su[EDG];

__device__ __forceinline__ float f2tf32(float x) {
    float y;
    asm("cvt.rna.tf32.f32 %0, %1;" : "=f"(y) : "f"(x));
    return y;
}

// ---------------------------------------------------------------------------
// Edge prep kernels
// ---------------------------------------------------------------------------
__global__ void k_gather2(const int* __restrict__ si, int* __restrict__ s2, int E) {
    int e = blockIdx.x * blockDim.x + threadIdx.x;
    if (e < E) {
        int a = si[e];
        s2[e] = si[a];
    }
}

__global__ void k_hist(const int* __restrict__ ti, int* __restrict__ cnt, int E) {
    int e = blockIdx.x * blockDim.x + threadIdx.x;
    if (e < E) atomicAdd(&cnt[ti[e]], 1);
}

__global__ void k_scan(const int* __restrict__ cnt, int* __restrict__ off,
                       int* __restrict__ cur, int n) {
    __shared__ int s[1024];
    int tid = threadIdx.x;
    int chunk = (n + 1023) / 1024;
    int beg = tid * chunk;
    int end = beg + chunk; if (end > n) end = n; if (beg > n) beg = n;
    int sum = 0;
    for (int i = beg; i < end; i++) sum += cnt[i];
    s[tid] = sum;
    __syncthreads();
    for (int d = 1; d < 1024; d <<= 1) {
        int v = 0;
        if (tid >= d) v = s[tid - d];
        __syncthreads();
        s[tid] += v;
        __syncthreads();
    }
    int run = s[tid] - sum;
    for (int i = beg; i < end; i++) {
        off[i] = run; cur[i] = run;
        run += cnt[i];
    }
    if (tid == 1023) off[n] = s[1023];
}

__global__ void k_scatter(const int* __restrict__ ti, const int* __restrict__ s2,
                          int* __restrict__ cur, int* __restrict__ csr, int E) {
    int e = blockIdx.x * blockDim.x + threadIdx.x;
    if (e < E) {
        int p = atomicAdd(&cur[ti[e]], 1);
        csr[p] = s2[e];
    }
}

// ---------------------------------------------------------------------------
// tf32 mma.sync GEMM: Y[M,BN] = X[M,K] @ W[K,BN]
// BM=64 rows/CTA, 256 threads = 8 warps as 2(M) x 4(N). Warp tile 32 x (BN/4).
// A smem: row-major [BM][K+4] (frag loads conflict-free: (K+4)%32==4).
// B smem: k-major  [K][BN+8] (staging coalesced; frag loads conflict-free:
//         (BN+8)%32==8 -> bank = t*8+q = lane).
// Optional fused alpha dot (smem-reduced) / bias.
// ---------------------------------------------------------------------------
template <int K, int BN, bool ALPHA, bool BIAS>
__global__ __launch_bounds__(256)
void k_gemm_tc(const float* __restrict__ X, const float* __restrict__ W,
               const float* __restrict__ avec, const float* __restrict__ bias,
               float* __restrict__ Y, float* __restrict__ alphaOut, int M) {
    constexpr int BM = 64;
    constexpr int KP = K + 4;
    constexpr int NP = BN + 8;
    constexpr int WN = BN / 4;
    constexpr int NT = WN / 8;
    extern __shared__ float smf[];
    float* As = smf;                   // [BM][KP]
    float* Bs = smf + BM * KP;         // [K][NP]

    const int tid = threadIdx.x;
    const int wid = tid >> 5;
    const int lane = tid & 31;
    const int warpM = wid >> 2;        // 0..1
    const int warpN = wid & 3;         // 0..3
    const int rowBase = blockIdx.x * BM;

    // ---- stage X tile [BM x K] (row-major, float4, conflict-free) ----
    for (int i = tid; i < BM * K / 4; i += 256) {
        int r = i / (K / 4);
        int c4 = (i % (K / 4)) * 4;
        float4 v = make_float4(0.f, 0.f, 0.f, 0.f);
        int gr = rowBase + r;
        if (gr < M) v = *(const float4*)(X + (size_t)gr * K + c4);
        v.x = f2tf32(v.x); v.y = f2tf32(v.y); v.z = f2tf32(v.z); v.w = f2tf32(v.w);
        *(float4*)(As + r * KP + c4) = v;
    }
    // ---- stage W [K x BN] (k-major, float4, coalesced + conflict-free) ----
    for (int i = tid; i < K * BN / 4; i += 256) {
        int k = i / (BN / 4);
        int n4 = (i % (BN / 4)) * 4;
        float4 v = *(const float4*)(W + (size_t)k * BN + n4);
        v.x = f2tf32(v.x); v.y = f2tf32(v.y); v.z = f2tf32(v.z); v.w = f2tf32(v.w);
        *(float4*)(Bs + k * NP + n4) = v;
    }
    __syncthreads();

    // ---- MMA mainloop ----
    float acc[2][NT][4];
#pragma unroll
    for (int mt = 0; mt < 2; mt++)
#pragma unroll
        for (int nt = 0; nt < NT; nt++)
#pragma unroll
            for (int j = 0; j < 4; j++) acc[mt][nt][j] = 0.f;

    const int q = lane >> 2;       // 0..7
    const int t = lane & 3;        // 0..3
    const uint32_t* Au = (const uint32_t*)As;
    const uint32_t* Bu = (const uint32_t*)Bs;

#pragma unroll
    for (int kk = 0; kk < K; kk += 8) {
        uint32_t a[2][4];
#pragma unroll
        for (int mt = 0; mt < 2; mt++) {
            int r0 = warpM * 32 + mt * 16 + q;
            a[mt][0] = Au[r0 * KP + kk + t];
            a[mt][1] = Au[(r0 + 8) * KP + kk + t];
            a[mt][2] = Au[r0 * KP + kk + 4 + t];
            a[mt][3] = Au[(r0 + 8) * KP + kk + 4 + t];
        }
        uint32_t b[NT][2];
#pragma unroll
        for (int nt = 0; nt < NT; nt++) {
            int nc = warpN * WN + nt * 8 + q;
            b[nt][0] = Bu[(kk + t) * NP + nc];
            b[nt][1] = Bu[(kk + 4 + t) * NP + nc];
        }
#pragma unroll
        for (int mt = 0; mt < 2; mt++)
#pragma unroll
            for (int nt = 0; nt < NT; nt++) {
                asm("mma.sync.aligned.m16n8k8.row.col.f32.tf32.tf32.f32 "
                    "{%0,%1,%2,%3}, {%4,%5,%6,%7}, {%8,%9}, {%0,%1,%2,%3};"
                    : "+f"(acc[mt][nt][0]), "+f"(acc[mt][nt][1]),
                      "+f"(acc[mt][nt][2]), "+f"(acc[mt][nt][3])
                    : "r"(a[mt][0]), "r"(a[mt][1]), "r"(a[mt][2]), "r"(a[mt][3]),
                      "r"(b[nt][0]), "r"(b[nt][1]));
            }
    }

    if (ALPHA) __syncthreads();    // done reading As/Bs; allow smem reuse below
    float* red = smf;              // [BM][5] alpha partials (aliases As)

    // ---- epilogue: stores (+ alpha partials) ----
#pragma unroll
    for (int mt = 0; mt < 2; mt++) {
        int lr0 = warpM * 32 + mt * 16 + q;       // local row, and +8
        int r0 = rowBase + lr0;
        float p0 = 0.f, p1 = 0.f;
#pragma unroll
        for (int nt = 0; nt < NT; nt++) {
            int cb = warpN * WN + nt * 8 + t * 2;
            float v0 = acc[mt][nt][0], v1 = acc[mt][nt][1];
            float v2 = acc[mt][nt][2], v3 = acc[mt][nt][3];
            if (BIAS) {
                v0 += bias[cb]; v1 += bias[cb + 1];
                v2 += bias[cb]; v3 += bias[cb + 1];
            }
            if (r0 < M) *(float2*)(Y + (size_t)r0 * BN + cb) = make_float2(v0, v1);
            if (r0 + 8 < M) *(float2*)(Y + (size_t)(r0 + 8) * BN + cb) = make_float2(v2, v3);
            if (ALPHA) {
                float a0 = avec[cb], a1 = avec[cb + 1];
                p0 += v0 * a0 + v1 * a1;
                p1 += v2 * a0 + v3 * a1;
            }
        }
        if (ALPHA) {
            p0 += __shfl_xor_sync(0xffffffffu, p0, 1);
            p0 += __shfl_xor_sync(0xffffffffu, p0, 2);
            p1 += __shfl_xor_sync(0xffffffffu, p1, 1);
            p1 += __shfl_xor_sync(0xffffffffu, p1, 2);
            if (t == 0) {
                red[lr0 * 5 + warpN] = p0;
                red[(lr0 + 8) * 5 + warpN] = p1;
            }
        }
    }
    if (ALPHA) {
        __syncthreads();
        if (tid < BM) {
            int gr = rowBase + tid;
            if (gr < M) {
                alphaOut[gr] = red[tid * 5 + 0] + red[tid * 5 + 1] +
                               red[tid * 5 + 2] + red[tid * 5 + 3];
            }
        }
    }
}

// ---------------------------------------------------------------------------
// Aggregation: one warp per target node.
// ---------------------------------------------------------------------------
__global__ __launch_bounds__(256)
void k_agg(const float4* __restrict__ tgt, const float4* __restrict__ src,
           const float* __restrict__ alpha_s, const float* __restrict__ alpha_t,
           const int* __restrict__ off, const int* __restrict__ csr,
           float4* __restrict__ out, int n) {
    int w = (blockIdx.x * blockDim.x + threadIdx.x) >> 5;
    int lid = threadIdx.x & 31;
    if (w >= n) return;
    float at = alpha_t[w];
    int beg = off[w];
    int end = off[w + 1];
    float4 acc = make_float4(0.f, 0.f, 0.f, 0.f);
    float den = 0.f;
    for (int j = beg; j < end; j++) {
        int s2 = csr[j];
        float l = alpha_s[s2] + at;
        l = (l > 0.f) ? l : LEAK * l;
        float a = __expf(l);
        den += a;
        float4 v = src[(size_t)s2 * 32 + lid];
        acc.x += a * v.x; acc.y += a * v.y; acc.z += a * v.z; acc.w += a * v.w;
    }
    float inv = 1.0f / (den + EPSF);
    float4 t = tgt[(size_t)w * 32 + lid];
    float4 r;
    r.x = fmaxf(t.x + acc.x * inv, 0.f);
    r.y = fmaxf(t.y + acc.y * inv, 0.f);
    r.z = fmaxf(t.z + acc.z * inv, 0.f);
    r.w = fmaxf(t.w + acc.w * inv, 0.f);
    out[(size_t)w * 32 + lid] = r;
}

// ---------------------------------------------------------------------------
// Host launcher
// ---------------------------------------------------------------------------
static inline float* symf(const void* sym) {
    void* p = nullptr;
    cudaGetSymbolAddress(&p, sym);
    return (float*)p;
}
static inline int* symi(const void* sym) {
    void* p = nullptr;
    cudaGetSymbolAddress(&p, sym);
    return (int*)p;
}

extern "C" void kernel_launch(void* const* d_in, const int* in_sizes, int n_in,
                              void* d_out, int out_size) {
    const float* x_user = (const float*)d_in[0];
    const float* x_spot = (const float*)d_in[1];
    const int*   e_us   = (const int*)d_in[2];
    const int*   e_su   = (const int*)d_in[3];
    const float* Ws_us0 = (const float*)d_in[4];
    const float* Wt_us0 = (const float*)d_in[5];
    const float* a_us0  = (const float*)d_in[6];
    const float* Ws_su0 = (const float*)d_in[7];
    const float* Wt_su0 = (const float*)d_in[8];
    const float* a_su0  = (const float*)d_in[9];
    const float* Ws_us1 = (const float*)d_in[10];
    const float* Wt_us1 = (const float*)d_in[11];
    const float* a_us1  = (const float*)d_in[12];
    const float* Ws_su1 = (const float*)d_in[13];
    const float* Wt_su1 = (const float*)d_in[14];
    const float* a_su1  = (const float*)d_in[15];
    const float* W_ou   = (const float*)d_in[16];
    const float* b_ou   = (const float*)d_in[17];
    const float* W_os   = (const float*)d_in[18];
    const float* b_os   = (const float*)d_in[19];

    float* out = (float*)d_out;
    float* xu_out = out;
    float* xs_out = out + (size_t)N_USER * HID;
    float* ou_out = xs_out + (size_t)N_SPOT * HID;
    float* os_out = ou_out + (size_t)N_USER * OUTC;

    float* srcA = symf(g_srcA); float* tgtA = symf(g_tgtA);
    float* srcB = symf(g_srcB); float* tgtB = symf(g_tgtB);
    float* hu = symf(g_hu);     float* hs = symf(g_hs);
    float* alsA = symf(g_alsA); float* altA = symf(g_altA);
    float* alsB = symf(g_alsB); float* altB = symf(g_altB);
    int* si2_us = symi(g_si2_us); int* si2_su = symi(g_si2_su);
    int* cnt_us = symi(g_cnt_us); int* off_us = symi(g_off_us); int* cur_us = symi(g_cur_us);
    int* cnt_su = symi(g_cnt_su); int* off_su = symi(g_off_su); int* cur_su = symi(g_cur_su);
    int* csr_us = symi(g_csr_us); int* csr_su = symi(g_csr_su);

    const int EB = (EDG + 255) / 256;
    const int G = (N_USER + 63) / 64;      // BM=64 tiles (same for spot)
    const int AU = (N_USER * 32 + 255) / 256;
    const int AS = (N_SPOT * 32 + 255) / 256;

    const int SM_L0 = (64 * (64 + 4) + 64 * (128 + 8)) * 4;      // 52.2 KB
    const int SM_L1 = (64 * (128 + 4) + 128 * (128 + 8)) * 4;    // 103.4 KB
    const int SM_FN = (64 * (128 + 4) + 128 * (64 + 8)) * 4;     // 70.7 KB

    cudaFuncSetAttribute((const void*)k_gemm_tc<64, 128, true, false>,
                         cudaFuncAttributeMaxDynamicSharedMemorySize, SM_L0);
    cudaFuncSetAttribute((const void*)k_gemm_tc<128, 128, true, false>,
                         cudaFuncAttributeMaxDynamicSharedMemorySize, SM_L1);
    cudaFuncSetAttribute((const void*)k_gemm_tc<128, 64, false, true>,
                         cudaFuncAttributeMaxDynamicSharedMemorySize, SM_FN);

    // ---- launch order puts an L0 GEMM at launch index 5 (ncu -s 5 -c 1) ----
    k_gather2<<<EB, 256>>>(e_us, si2_us, EDG);                               // 0
    k_gather2<<<EB, 256>>>(e_su, si2_su, EDG);                               // 1
    cudaMemsetAsync(cnt_us, 0, sizeof(int) * (N_SPOT + 1));                  // 2
    cudaMemsetAsync(cnt_su, 0, sizeof(int) * (N_USER + 1));                  // 3
    k_hist<<<EB, 256>>>(e_us + EDG, cnt_us, EDG);                            // 4
    k_gemm_tc<64, 128, true, false><<<G, 256, SM_L0>>>(                      // 5 (profiled)
        x_user, Ws_us0, a_us0, nullptr, srcA, alsA, N_USER);
    k_hist<<<EB, 256>>>(e_su + EDG, cnt_su, EDG);
    k_scan<<<1, 1024>>>(cnt_us, off_us, cur_us, N_SPOT);
    k_scan<<<1, 1024>>>(cnt_su, off_su, cur_su, N_USER);
    k_scatter<<<EB, 256>>>(e_us + EDG, si2_us, cur_us, csr_us, EDG);
    k_scatter<<<EB, 256>>>(e_su + EDG, si2_su, cur_su, csr_su, EDG);

    // ---- layer 0 (K=64), remaining ----
    k_gemm_tc<64, 128, true, false><<<G, 256, SM_L0>>>(x_spot, Wt_us0, a_us0 + HID, nullptr, tgtA, altA, N_SPOT);
    k_gemm_tc<64, 128, true, false><<<G, 256, SM_L0>>>(x_spot, Ws_su0, a_su0,       nullptr, srcB, alsB, N_SPOT);
    k_gemm_tc<64, 128, true, false><<<G, 256, SM_L0>>>(x_user, Wt_su0, a_su0 + HID, nullptr, tgtB, altB, N_USER);
    k_agg<<<AS, 256>>>((const float4*)tgtA, (const float4*)srcA, alsA, altA,
                       off_us, csr_us, (float4*)hs, N_SPOT);
    k_agg<<<AU, 256>>>((const float4*)tgtB, (const float4*)srcB, alsB, altB,
                       off_su, csr_su, (float4*)hu, N_USER);

    // ---- layer 1 (K=128) ----
    k_gemm_tc<128, 128, true, false><<<G, 256, SM_L1>>>(hu, Ws_us1, a_us1,       nullptr, srcA, alsA, N_USER);
    k_gemm_tc<128, 128, true, false><<<G, 256, SM_L1>>>(hs, Wt_us1, a_us1 + HID, nullptr, tgtA, altA, N_SPOT);
    k_gemm_tc<128, 128, true, false><<<G, 256, SM_L1>>>(hs, Ws_su1, a_su1,       nullptr, srcB, alsB, N_SPOT);
    k_gemm_tc<128, 128, true, false><<<G, 256, SM_L1>>>(hu, Wt_su1, a_su1 + HID, nullptr, tgtB, altB, N_USER);
    k_agg<<<AS, 256>>>((const float4*)tgtA, (const float4*)srcA, alsA, altA,
                       off_us, csr_us, (float4*)xs_out, N_SPOT);
    k_agg<<<AU, 256>>>((const float4*)tgtB, (const float4*)srcB, alsB, altB,
                       off_su, csr_su, (float4*)xu_out, N_USER);

    // ---- final per-type linear (K=128, N=64, bias) ----
    k_gemm_tc<128, 64, false, true><<<G, 256, SM_FN>>>(xu_out, W_ou, nullptr, b_ou, ou_out, nullptr, N_USER);
    k_gemm_tc<128, 64, false, true><<<G, 256, SM_FN>>>(xs_out, W_os, nullptr, b_os, os_out, nullptr, N_SPOT);
}

// round 6
// speedup vs baseline: 1.5767x; 1.2249x over previous
#include <cuda_runtime.h>
#include <cuda_bf16.h>
#include <cstdint>

#define N_USER 100000
#define N_SPOT 100000
#define F_IN   64
#define HID    128
#define OUTC   64
#define EDG    500000
#define LEAK   0.2f
#define EPSF   1e-6f

// ---------------------------------------------------------------------------
// Scratch (device globals; no allocation allowed)
// ---------------------------------------------------------------------------
__device__ float g_srcA[(size_t)N_USER * HID];
__device__ float g_tgtA[(size_t)N_SPOT * HID];
__device__ float g_srcB[(size_t)N_SPOT * HID];
__device__ float g_tgtB[(size_t)N_USER * HID];
__device__ float g_hu[(size_t)N_USER * HID];
__device__ float g_hs[(size_t)N_SPOT * HID];

__device__ float g_alsA[N_USER];
__device__ float g_altA[N_SPOT];
__device__ float g_alsB[N_SPOT];
__device__ float g_altB[N_USER];

__device__ int g_si2_us[EDG];
__device__ int g_si2_su[EDG];
__device__ int g_cnt_us[N_SPOT + 1];
__device__ int g_off_us[N_SPOT + 1];
__device__ int g_cur_us[N_SPOT + 1];
__device__ int g_cnt_su[N_USER + 1];
__device__ int g_off_su[N_USER + 1];
__device__ int g_cur_su[N_USER + 1];
__device__ int g_csr_us[EDG];
__device__ int g_csr_su[EDG];

__device__ __forceinline__ float f2tf32(float x) {
    float y;
    asm("cvt.rna.tf32.f32 %0, %1;" : "=f"(y) : "f"(x));
    return y;
}

// ---------------------------------------------------------------------------
// Edge prep kernels
// ---------------------------------------------------------------------------
__global__ void k_gather2(const int* __restrict__ si, int* __restrict__ s2, int E) {
    int e = blockIdx.x * blockDim.x + threadIdx.x;
    if (e < E) {
        int a = si[e];
        s2[e] = si[a];
    }
}

__global__ void k_hist(const int* __restrict__ ti, int* __restrict__ cnt, int E) {
    int e = blockIdx.x * blockDim.x + threadIdx.x;
    if (e < E) atomicAdd(&cnt[ti[e]], 1);
}

__global__ void k_scan(const int* __restrict__ cnt, int* __restrict__ off,
                       int* __restrict__ cur, int n) {
    __shared__ int s[1024];
    int tid = threadIdx.x;
    int chunk = (n + 1023) / 1024;
    int beg = tid * chunk;
    int end = beg + chunk; if (end > n) end = n; if (beg > n) beg = n;
    int sum = 0;
    for (int i = beg; i < end; i++) sum += cnt[i];
    s[tid] = sum;
    __syncthreads();
    for (int d = 1; d < 1024; d <<= 1) {
        int v = 0;
        if (tid >= d) v = s[tid - d];
        __syncthreads();
        s[tid] += v;
        __syncthreads();
    }
    int run = s[tid] - sum;
    for (int i = beg; i < end; i++) {
        off[i] = run; cur[i] = run;
        run += cnt[i];
    }
    if (tid == 1023) off[n] = s[1023];
}

__global__ void k_scatter(const int* __restrict__ ti, const int* __restrict__ s2,
                          int* __restrict__ cur, int* __restrict__ csr, int E) {
    int e = blockIdx.x * blockDim.x + threadIdx.x;
    if (e < E) {
        int p = atomicAdd(&cur[ti[e]], 1);
        csr[p] = s2[e];
    }
}

// ---------------------------------------------------------------------------
// Persistent tf32 mma.sync GEMM: Y[M,BN] = X[M,K] @ W[K,BN]
// Grid = fixed 296 CTAs; each CTA loops over BM=64-row tiles.
// W staged ONCE per CTA (k-major [K][BN+8], conflict-free).
// X tile double-lived: next tile prefetched into registers during compute.
// Optional fused alpha dot (smem-reduced) / bias.
// ---------------------------------------------------------------------------
template <int K, int BN, bool ALPHA, bool BIAS>
__global__ __launch_bounds__(256)
void k_gemm_tc(const float* __restrict__ X, const float* __restrict__ W,
               const float* __restrict__ avec, const float* __restrict__ bias,
               float* __restrict__ Y, float* __restrict__ alphaOut, int M) {
    constexpr int BM = 64;
    constexpr int KP = K + 4;
    constexpr int NP = BN + 8;
    constexpr int WN = BN / 4;
    constexpr int NT = WN / 8;
    constexpr int XF = BM * K / 1024;     // float4 per thread for an X tile
    extern __shared__ float smf[];
    float* Wsm = smf;                     // [K][NP]
    float* As  = smf + K * NP;            // [BM][KP]
    float* red = As + BM * KP;            // [BM][5]

    const int tid = threadIdx.x;
    const int wid = tid >> 5;
    const int lane = tid & 31;
    const int warpM = wid >> 2;
    const int warpN = wid & 3;
    const int q = lane >> 2;
    const int t = lane & 3;

    // ---- stage W once (k-major, coalesced, conflict-free) ----
    for (int i = tid; i < K * BN / 4; i += 256) {
        int k = i / (BN / 4);
        int n4 = (i % (BN / 4)) * 4;
        float4 v = *(const float4*)(W + (size_t)k * BN + n4);
        v.x = f2tf32(v.x); v.y = f2tf32(v.y); v.z = f2tf32(v.z); v.w = f2tf32(v.w);
        *(float4*)(Wsm + k * NP + n4) = v;
    }

    const int ntiles = (M + BM - 1) / BM;
    int tile = blockIdx.x;
    float4 xr[XF];

    // prologue: load first tile into registers
    if (tile < ntiles) {
#pragma unroll
        for (int f = 0; f < XF; f++) {
            int i = tid + f * 256;
            int r = i / (K / 4);
            int c4 = (i % (K / 4)) * 4;
            int gr = tile * BM + r;
            xr[f] = (gr < M) ? *(const float4*)(X + (size_t)gr * K + c4)
                             : make_float4(0.f, 0.f, 0.f, 0.f);
        }
    }
    __syncthreads();   // W ready

    for (; tile < ntiles; tile += gridDim.x) {
        // ---- commit registers -> As (with tf32 convert) ----
#pragma unroll
        for (int f = 0; f < XF; f++) {
            int i = tid + f * 256;
            int r = i / (K / 4);
            int c4 = (i % (K / 4)) * 4;
            float4 v = xr[f];
            v.x = f2tf32(v.x); v.y = f2tf32(v.y); v.z = f2tf32(v.z); v.w = f2tf32(v.w);
            *(float4*)(As + r * KP + c4) = v;
        }
        __syncthreads();

        // ---- prefetch next tile while computing this one ----
        int next = tile + gridDim.x;
        if (next < ntiles) {
#pragma unroll
            for (int f = 0; f < XF; f++) {
                int i = tid + f * 256;
                int r = i / (K / 4);
                int c4 = (i % (K / 4)) * 4;
                int gr = next * BM + r;
                xr[f] = (gr < M) ? *(const float4*)(X + (size_t)gr * K + c4)
                                 : make_float4(0.f, 0.f, 0.f, 0.f);
            }
        }

        // ---- MMA mainloop ----
        float acc[2][NT][4];
#pragma unroll
        for (int mt = 0; mt < 2; mt++)
#pragma unroll
            for (int nt = 0; nt < NT; nt++)
#pragma unroll
                for (int j = 0; j < 4; j++) acc[mt][nt][j] = 0.f;

        const uint32_t* Au = (const uint32_t*)As;
        const uint32_t* Bu = (const uint32_t*)Wsm;

#pragma unroll
        for (int kk = 0; kk < K; kk += 8) {
            uint32_t a[2][4];
#pragma unroll
            for (int mt = 0; mt < 2; mt++) {
                int r0 = warpM * 32 + mt * 16 + q;
                a[mt][0] = Au[r0 * KP + kk + t];
                a[mt][1] = Au[(r0 + 8) * KP + kk + t];
                a[mt][2] = Au[r0 * KP + kk + 4 + t];
                a[mt][3] = Au[(r0 + 8) * KP + kk + 4 + t];
            }
            uint32_t b[NT][2];
#pragma unroll
            for (int nt = 0; nt < NT; nt++) {
                int nc = warpN * WN + nt * 8 + q;
                b[nt][0] = Bu[(kk + t) * NP + nc];
                b[nt][1] = Bu[(kk + 4 + t) * NP + nc];
            }
#pragma unroll
            for (int mt = 0; mt < 2; mt++)
#pragma unroll
                for (int nt = 0; nt < NT; nt++) {
                    asm("mma.sync.aligned.m16n8k8.row.col.f32.tf32.tf32.f32 "
                        "{%0,%1,%2,%3}, {%4,%5,%6,%7}, {%8,%9}, {%0,%1,%2,%3};"
                        : "+f"(acc[mt][nt][0]), "+f"(acc[mt][nt][1]),
                          "+f"(acc[mt][nt][2]), "+f"(acc[mt][nt][3])
                        : "r"(a[mt][0]), "r"(a[mt][1]), "r"(a[mt][2]), "r"(a[mt][3]),
                          "r"(b[nt][0]), "r"(b[nt][1]));
                }
        }

        // ---- epilogue ----
        const int rowBase = tile * BM;
#pragma unroll
        for (int mt = 0; mt < 2; mt++) {
            int lr0 = warpM * 32 + mt * 16 + q;
            int r0 = rowBase + lr0;
            float p0 = 0.f, p1 = 0.f;
#pragma unroll
            for (int nt = 0; nt < NT; nt++) {
                int cb = warpN * WN + nt * 8 + t * 2;
                float v0 = acc[mt][nt][0], v1 = acc[mt][nt][1];
                float v2 = acc[mt][nt][2], v3 = acc[mt][nt][3];
                if (BIAS) {
                    v0 += bias[cb]; v1 += bias[cb + 1];
                    v2 += bias[cb]; v3 += bias[cb + 1];
                }
                if (r0 < M) *(float2*)(Y + (size_t)r0 * BN + cb) = make_float2(v0, v1);
                if (r0 + 8 < M) *(float2*)(Y + (size_t)(r0 + 8) * BN + cb) = make_float2(v2, v3);
                if (ALPHA) {
                    float a0 = avec[cb], a1 = avec[cb + 1];
                    p0 += v0 * a0 + v1 * a1;
                    p1 += v2 * a0 + v3 * a1;
                }
            }
            if (ALPHA) {
                p0 += __shfl_xor_sync(0xffffffffu, p0, 1);
                p0 += __shfl_xor_sync(0xffffffffu, p0, 2);
                p1 += __shfl_xor_sync(0xffffffffu, p1, 1);
                p1 += __shfl_xor_sync(0xffffffffu, p1, 2);
                if (t == 0) {
                    red[lr0 * 5 + warpN] = p0;
                    red[(lr0 + 8) * 5 + warpN] = p1;
                }
            }
        }
        __syncthreads();   // epilogue done; As reads finished; red visible
        if (ALPHA) {
            if (tid < BM) {
                int gr = rowBase + tid;
                if (gr < M) {
                    alphaOut[gr] = red[tid * 5 + 0] + red[tid * 5 + 1] +
                                   red[tid * 5 + 2] + red[tid * 5 + 3];
                }
            }
            __syncthreads();  // red reads done before next tile overwrites? (red not overwritten by As store; keep for safety vs As reuse)
        }
    }
}

// ---------------------------------------------------------------------------
// Aggregation: one warp per target node, unroll-4 for MLP.
// ---------------------------------------------------------------------------
__global__ __launch_bounds__(256)
void k_agg(const float4* __restrict__ tgt, const float4* __restrict__ src,
           const float* __restrict__ alpha_s, const float* __restrict__ alpha_t,
           const int* __restrict__ off, const int* __restrict__ csr,
           float4* __restrict__ out, int n) {
    int w = (blockIdx.x * blockDim.x + threadIdx.x) >> 5;
    int lid = threadIdx.x & 31;
    if (w >= n) return;
    float at = alpha_t[w];
    int beg = off[w];
    int end = off[w + 1];
    float4 acc = make_float4(0.f, 0.f, 0.f, 0.f);
    float den = 0.f;
    int j = beg;
    // 4-wide: batch index + alpha + row loads for MLP
    for (; j + 3 < end; j += 4) {
        int s0 = csr[j + 0], s1 = csr[j + 1], s2 = csr[j + 2], s3 = csr[j + 3];
        float b0 = alpha_s[s0], b1 = alpha_s[s1], b2 = alpha_s[s2], b3 = alpha_s[s3];
        float4 v0 = src[(size_t)s0 * 32 + lid];
        float4 v1 = src[(size_t)s1 * 32 + lid];
        float4 v2 = src[(size_t)s2 * 32 + lid];
        float4 v3 = src[(size_t)s3 * 32 + lid];
        float l0 = b0 + at; l0 = (l0 > 0.f) ? l0 : LEAK * l0;
        float l1 = b1 + at; l1 = (l1 > 0.f) ? l1 : LEAK * l1;
        float l2 = b2 + at; l2 = (l2 > 0.f) ? l2 : LEAK * l2;
        float l3 = b3 + at; l3 = (l3 > 0.f) ? l3 : LEAK * l3;
        float a0 = __expf(l0), a1 = __expf(l1), a2 = __expf(l2), a3 = __expf(l3);
        den += (a0 + a1) + (a2 + a3);
        acc.x += a0 * v0.x + a1 * v1.x + a2 * v2.x + a3 * v3.x;
        acc.y += a0 * v0.y + a1 * v1.y + a2 * v2.y + a3 * v3.y;
        acc.z += a0 * v0.z + a1 * v1.z + a2 * v2.z + a3 * v3.z;
        acc.w += a0 * v0.w + a1 * v1.w + a2 * v2.w + a3 * v3.w;
    }
    if (j + 1 < end) {   // 2-wide tail
        int s0 = csr[j + 0], s1 = csr[j + 1];
        float b0 = alpha_s[s0], b1 = alpha_s[s1];
        float4 v0 = src[(size_t)s0 * 32 + lid];
        float4 v1 = src[(size_t)s1 * 32 + lid];
        float l0 = b0 + at; l0 = (l0 > 0.f) ? l0 : LEAK * l0;
        float l1 = b1 + at; l1 = (l1 > 0.f) ? l1 : LEAK * l1;
        float a0 = __expf(l0), a1 = __expf(l1);
        den += a0 + a1;
        acc.x += a0 * v0.x + a1 * v1.x;
        acc.y += a0 * v0.y + a1 * v1.y;
        acc.z += a0 * v0.z + a1 * v1.z;
        acc.w += a0 * v0.w + a1 * v1.w;
        j += 2;
    }
    if (j < end) {       // single tail
        int s0 = csr[j];
        float b0 = alpha_s[s0];
        float4 v0 = src[(size_t)s0 * 32 + lid];
        float l0 = b0 + at; l0 = (l0 > 0.f) ? l0 : LEAK * l0;
        float a0 = __expf(l0);
        den += a0;
        acc.x += a0 * v0.x; acc.y += a0 * v0.y;
        acc.z += a0 * v0.z; acc.w += a0 * v0.w;
    }
    float inv = 1.0f / (den + EPSF);
    float4 tv = tgt[(size_t)w * 32 + lid];
    float4 r;
    r.x = fmaxf(tv.x + acc.x * inv, 0.f);
    r.y = fmaxf(tv.y + acc.y * inv, 0.f);
    r.z = fmaxf(tv.z + acc.z * inv, 0.f);
    r.w = fmaxf(tv.w + acc.w * inv, 0.f);
    out[(size_t)w * 32 + lid] = r;
}

// ---------------------------------------------------------------------------
// Host launcher
// ---------------------------------------------------------------------------
static inline float* symf(const void* sym) {
    void* p = nullptr;
    cudaGetSymbolAddress(&p, sym);
    return (float*)p;
}
static inline int* symi(const void* sym) {
    void* p = nullptr;
    cudaGetSymbolAddress(&p, sym);
    return (int*)p;
}

extern "C" void kernel_launch(void* const* d_in, const int* in_sizes, int n_in,
                              void* d_out, int out_size) {
    const float* x_user = (const float*)d_in[0];
    const float* x_spot = (const float*)d_in[1];
    const int*   e_us   = (const int*)d_in[2];
    const int*   e_su   = (const int*)d_in[3];
    const float* Ws_us0 = (const float*)d_in[4];
    const float* Wt_us0 = (const float*)d_in[5];
    const float* a_us0  = (const float*)d_in[6];
    const float* Ws_su0 = (const float*)d_in[7];
    const float* Wt_su0 = (const float*)d_in[8];
    const float* a_su0  = (const float*)d_in[9];
    const float* Ws_us1 = (const float*)d_in[10];
    const float* Wt_us1 = (const float*)d_in[11];
    const float* a_us1  = (const float*)d_in[12];
    const float* Ws_su1 = (const float*)d_in[13];
    const float* Wt_su1 = (const float*)d_in[14];
    const float* a_su1  = (const float*)d_in[15];
    const float* W_ou   = (const float*)d_in[16];
    const float* b_ou   = (const float*)d_in[17];
    const float* W_os   = (const float*)d_in[18];
    const float* b_os   = (const float*)d_in[19];

    float* out = (float*)d_out;
    float* xu_out = out;
    float* xs_out = out + (size_t)N_USER * HID;
    float* ou_out = xs_out + (size_t)N_SPOT * HID;
    float* os_out = ou_out + (size_t)N_USER * OUTC;

    float* srcA = symf(g_srcA); float* tgtA = symf(g_tgtA);
    float* srcB = symf(g_srcB); float* tgtB = symf(g_tgtB);
    float* hu = symf(g_hu);     float* hs = symf(g_hs);
    float* alsA = symf(g_alsA); float* altA = symf(g_altA);
    float* alsB = symf(g_alsB); float* altB = symf(g_altB);
    int* si2_us = symi(g_si2_us); int* si2_su = symi(g_si2_su);
    int* cnt_us = symi(g_cnt_us); int* off_us = symi(g_off_us); int* cur_us = symi(g_cur_us);
    int* cnt_su = symi(g_cnt_su); int* off_su = symi(g_off_su); int* cur_su = symi(g_cur_su);
    int* csr_us = symi(g_csr_us); int* csr_su = symi(g_csr_su);

    const int EB = (EDG + 255) / 256;
    const int GP = 296;                    // persistent grid: 2 CTAs/SM x 148
    const int AU = (N_USER * 32 + 255) / 256;
    const int AS = (N_SPOT * 32 + 255) / 256;

    const int SM_L0 = (64 * (128 + 8) + 64 * (64 + 4) + 64 * 5) * 4;     // ~53.5 KB
    const int SM_L1 = (128 * (128 + 8) + 64 * (128 + 4) + 64 * 5) * 4;   // ~104.7 KB
    const int SM_FN = (128 * (64 + 8) + 64 * (128 + 4) + 64 * 5) * 4;    // ~71.9 KB

    cudaFuncSetAttribute((const void*)k_gemm_tc<64, 128, true, false>,
                         cudaFuncAttributeMaxDynamicSharedMemorySize, SM_L0);
    cudaFuncSetAttribute((const void*)k_gemm_tc<128, 128, true, false>,
                         cudaFuncAttributeMaxDynamicSharedMemorySize, SM_L1);
    cudaFuncSetAttribute((const void*)k_gemm_tc<128, 64, false, true>,
                         cudaFuncAttributeMaxDynamicSharedMemorySize, SM_FN);

    // ---- launch order keeps an L0 GEMM at launch index 5 (ncu -s 5 -c 1) ----
    k_gather2<<<EB, 256>>>(e_us, si2_us, EDG);                               // 0
    k_gather2<<<EB, 256>>>(e_su, si2_su, EDG);                               // 1
    cudaMemsetAsync(cnt_us, 0, sizeof(int) * (N_SPOT + 1));                  // 2
    cudaMemsetAsync(cnt_su, 0, sizeof(int) * (N_USER + 1));                  // 3
    k_hist<<<EB, 256>>>(e_us + EDG, cnt_us, EDG);                            // 4
    k_gemm_tc<64, 128, true, false><<<GP, 256, SM_L0>>>(                     // 5 (profiled)
        x_user, Ws_us0, a_us0, nullptr, srcA, alsA, N_USER);
    k_hist<<<EB, 256>>>(e_su + EDG, cnt_su, EDG);
    k_scan<<<1, 1024>>>(cnt_us, off_us, cur_us, N_SPOT);
    k_scan<<<1, 1024>>>(cnt_su, off_su, cur_su, N_USER);
    k_scatter<<<EB, 256>>>(e_us + EDG, si2_us, cur_us, csr_us, EDG);
    k_scatter<<<EB, 256>>>(e_su + EDG, si2_su, cur_su, csr_su, EDG);

    // ---- layer 0 (K=64), remaining ----
    k_gemm_tc<64, 128, true, false><<<GP, 256, SM_L0>>>(x_spot, Wt_us0, a_us0 + HID, nullptr, tgtA, altA, N_SPOT);
    k_gemm_tc<64, 128, true, false><<<GP, 256, SM_L0>>>(x_spot, Ws_su0, a_su0,       nullptr, srcB, alsB, N_SPOT);
    k_gemm_tc<64, 128, true, false><<<GP, 256, SM_L0>>>(x_user, Wt_su0, a_su0 + HID, nullptr, tgtB, altB, N_USER);
    k_agg<<<AS, 256>>>((const float4*)tgtA, (const float4*)srcA, alsA, altA,
                       off_us, csr_us, (float4*)hs, N_SPOT);
    k_agg<<<AU, 256>>>((const float4*)tgtB, (const float4*)srcB, alsB, altB,
                       off_su, csr_su, (float4*)hu, N_USER);

    // ---- layer 1 (K=128) ----
    k_gemm_tc<128, 128, true, false><<<GP, 256, SM_L1>>>(hu, Ws_us1, a_us1,       nullptr, srcA, alsA, N_USER);
    k_gemm_tc<128, 128, true, false><<<GP, 256, SM_L1>>>(hs, Wt_us1, a_us1 + HID, nullptr, tgtA, altA, N_SPOT);
    k_gemm_tc<128, 128, true, false><<<GP, 256, SM_L1>>>(hs, Ws_su1, a_su1,       nullptr, srcB, alsB, N_SPOT);
    k_gemm_tc<128, 128, true, false><<<GP, 256, SM_L1>>>(hu, Wt_su1, a_su1 + HID, nullptr, tgtB, altB, N_USER);
    k_agg<<<AS, 256>>>((const float4*)tgtA, (const float4*)srcA, alsA, altA,
                       off_us, csr_us, (float4*)xs_out, N_SPOT);
    k_agg<<<AU, 256>>>((const float4*)tgtB, (const float4*)srcB, alsB, altB,
                       off_su, csr_su, (float4*)xu_out, N_USER);

    // ---- final per-type linear (K=128, N=64, bias) ----
    k_gemm_tc<128, 64, false, true><<<GP, 256, SM_FN>>>(xu_out, W_ou, nullptr, b_ou, ou_out, nullptr, N_USER);
    k_gemm_tc<128, 64, false, true><<<GP, 256, SM_FN>>>(xs_out, W_os, nullptr, b_os, os_out, nullptr, N_SPOT);
}

// round 7
// speedup vs baseline: 1.6748x; 1.0622x over previous
#include <cuda_runtime.h>
#include <cuda_bf16.h>
#include <cstdint>

#define N_USER 100000
#define N_SPOT 100000
#define F_IN   64
#define HID    128
#define OUTC   64
#define EDG    500000
#define LEAK   0.2f
#define EPSF   1e-6f

// ---------------------------------------------------------------------------
// Scratch (device globals; no allocation allowed)
// ---------------------------------------------------------------------------
__device__ float g_srcA[(size_t)N_USER * HID];
__device__ float g_tgtA[(size_t)N_SPOT * HID];
__device__ float g_srcB[(size_t)N_SPOT * HID];
__device__ float g_tgtB[(size_t)N_USER * HID];
__device__ float g_hu[(size_t)N_USER * HID];
__device__ float g_hs[(size_t)N_SPOT * HID];

__device__ float g_alsA[N_USER];
__device__ float g_altA[N_SPOT];
__device__ float g_alsB[N_SPOT];
__device__ float g_altB[N_USER];

__device__ int g_si2_us[EDG];
__device__ int g_si2_su[EDG];
__device__ int g_cnt_us[N_SPOT + 1];
__device__ int g_off_us[N_SPOT + 1];
__device__ int g_cur_us[N_SPOT + 1];
__device__ int g_cnt_su[N_USER + 1];
__device__ int g_off_su[N_USER + 1];
__device__ int g_cur_su[N_USER + 1];
__device__ int g_csr_us[EDG];     // source ids in CSR-by-target order
__device__ int g_csr_su[EDG];
__device__ int g_row_us[EDG];     // target id per CSR slot
__device__ int g_row_su[EDG];
__device__ float g_att[EDG];      // per-conv edge attention (reused 4x)

__device__ __forceinline__ float f2tf32(float x) {
    float y;
    asm("cvt.rna.tf32.f32 %0, %1;" : "=f"(y) : "f"(x));
    return y;
}

// ---------------------------------------------------------------------------
// Edge prep kernels
// ---------------------------------------------------------------------------
__global__ void k_gather2(const int* __restrict__ si, int* __restrict__ s2, int E) {
    int e = blockIdx.x * blockDim.x + threadIdx.x;
    if (e < E) {
        int a = si[e];
        s2[e] = si[a];
    }
}

__global__ void k_hist(const int* __restrict__ ti, int* __restrict__ cnt, int E) {
    int e = blockIdx.x * blockDim.x + threadIdx.x;
    if (e < E) atomicAdd(&cnt[ti[e]], 1);
}

__global__ void k_scan(const int* __restrict__ cnt, int* __restrict__ off,
                       int* __restrict__ cur, int n) {
    __shared__ int s[1024];
    int tid = threadIdx.x;
    int chunk = (n + 1023) / 1024;
    int beg = tid * chunk;
    int end = beg + chunk; if (end > n) end = n; if (beg > n) beg = n;
    int sum = 0;
    for (int i = beg; i < end; i++) sum += cnt[i];
    s[tid] = sum;
    __syncthreads();
    for (int d = 1; d < 1024; d <<= 1) {
        int v = 0;
        if (tid >= d) v = s[tid - d];
        __syncthreads();
        s[tid] += v;
        __syncthreads();
    }
    int run = s[tid] - sum;
    for (int i = beg; i < end; i++) {
        off[i] = run; cur[i] = run;
        run += cnt[i];
    }
    if (tid == 1023) off[n] = s[1023];
}

__global__ void k_scatter(const int* __restrict__ ti, const int* __restrict__ s2,
                          int* __restrict__ cur, int* __restrict__ csr,
                          int* __restrict__ rowOf, int E) {
    int e = blockIdx.x * blockDim.x + threadIdx.x;
    if (e < E) {
        int t = ti[e];
        int p = atomicAdd(&cur[t], 1);
        csr[p] = s2[e];
        rowOf[p] = t;
    }
}

// Edge attention: att[j] = exp(leaky_relu(alpha_s[csr[j]] + alpha_t[rowOf[j]]))
__global__ void k_att(const int* __restrict__ csr, const int* __restrict__ rowOf,
                      const float* __restrict__ alpha_s, const float* __restrict__ alpha_t,
                      float* __restrict__ att, int E) {
    int j = blockIdx.x * blockDim.x + threadIdx.x;
    if (j < E) {
        float l = alpha_s[csr[j]] + alpha_t[rowOf[j]];
        l = (l > 0.f) ? l : LEAK * l;
        att[j] = __expf(l);
    }
}

// ---------------------------------------------------------------------------
// Persistent tf32 mma.sync GEMM.
//   N=256 (dual): Y0 = X@W0 (cols 0-127), Y1 = X@W1 (cols 128-255),
//                 fused alpha dots al0 = Y0.av0, al1 = Y1.av1.
//   N=64: single output + bias.
// Grid persistent; W staged once per CTA; X tile register-prefetched.
// 8 warps as 2(M) x 4(N); warp tile 32 x (N/4).
// ---------------------------------------------------------------------------
template <int K, int N, bool ALPHA, bool BIAS>
__global__ __launch_bounds__(256)
void k_gemm_tc(const float* __restrict__ X,
               const float* __restrict__ W0, const float* __restrict__ W1,
               const float* __restrict__ av0, const float* __restrict__ av1,
               const float* __restrict__ bias,
               float* __restrict__ Y0, float* __restrict__ Y1,
               float* __restrict__ al0, float* __restrict__ al1, int M) {
    constexpr int BM = 64;
    constexpr int KP = K + 4;
    constexpr int NP = N + 8;
    constexpr int WN = N / 4;
    constexpr int NT = WN / 8;
    constexpr int XF = BM * K / 1024;
    extern __shared__ float smf[];
    float* Wsm = smf;                     // [K][NP]
    float* As  = smf + K * NP;            // [BM][KP]
    float* red = As + BM * KP;            // [BM][5]

    const int tid = threadIdx.x;
    const int wid = tid >> 5;
    const int lane = tid & 31;
    const int warpM = wid >> 2;
    const int warpN = wid & 3;
    const int q = lane >> 2;
    const int t = lane & 3;

    // ---- stage W once (k-major; dual: [W0 | W1]) ----
    for (int i = tid; i < K * N / 4; i += 256) {
        int k = i / (N / 4);
        int n4 = (i % (N / 4)) * 4;
        const float* src = (N == 256)
            ? ((n4 < 128) ? (W0 + (size_t)k * 128 + n4) : (W1 + (size_t)k * 128 + (n4 - 128)))
            : (W0 + (size_t)k * N + n4);
        float4 v = *(const float4*)src;
        v.x = f2tf32(v.x); v.y = f2tf32(v.y); v.z = f2tf32(v.z); v.w = f2tf32(v.w);
        *(float4*)(Wsm + k * NP + n4) = v;
    }

    const int ntiles = (M + BM - 1) / BM;
    int tile = blockIdx.x;
    float4 xr[XF];

    if (tile < ntiles) {
#pragma unroll
        for (int f = 0; f < XF; f++) {
            int i = tid + f * 256;
            int r = i / (K / 4);
            int c4 = (i % (K / 4)) * 4;
            int gr = tile * BM + r;
            xr[f] = (gr < M) ? *(const float4*)(X + (size_t)gr * K + c4)
                             : make_float4(0.f, 0.f, 0.f, 0.f);
        }
    }
    __syncthreads();   // W ready

    for (; tile < ntiles; tile += gridDim.x) {
#pragma unroll
        for (int f = 0; f < XF; f++) {
            int i = tid + f * 256;
            int r = i / (K / 4);
            int c4 = (i % (K / 4)) * 4;
            float4 v = xr[f];
            v.x = f2tf32(v.x); v.y = f2tf32(v.y); v.z = f2tf32(v.z); v.w = f2tf32(v.w);
            *(float4*)(As + r * KP + c4) = v;
        }
        __syncthreads();

        int next = tile + gridDim.x;
        if (next < ntiles) {
#pragma unroll
            for (int f = 0; f < XF; f++) {
                int i = tid + f * 256;
                int r = i / (K / 4);
                int c4 = (i % (K / 4)) * 4;
                int gr = next * BM + r;
                xr[f] = (gr < M) ? *(const float4*)(X + (size_t)gr * K + c4)
                                 : make_float4(0.f, 0.f, 0.f, 0.f);
            }
        }

        float acc[2][NT][4];
#pragma unroll
        for (int mt = 0; mt < 2; mt++)
#pragma unroll
            for (int nt = 0; nt < NT; nt++)
#pragma unroll
                for (int j = 0; j < 4; j++) acc[mt][nt][j] = 0.f;

        const uint32_t* Au = (const uint32_t*)As;
        const uint32_t* Bu = (const uint32_t*)Wsm;

#pragma unroll
        for (int kk = 0; kk < K; kk += 8) {
            uint32_t a[2][4];
#pragma unroll
            for (int mt = 0; mt < 2; mt++) {
                int r0 = warpM * 32 + mt * 16 + q;
                a[mt][0] = Au[r0 * KP + kk + t];
                a[mt][1] = Au[(r0 + 8) * KP + kk + t];
                a[mt][2] = Au[r0 * KP + kk + 4 + t];
                a[mt][3] = Au[(r0 + 8) * KP + kk + 4 + t];
            }
            uint32_t b[NT][2];
#pragma unroll
            for (int nt = 0; nt < NT; nt++) {
                int nc = warpN * WN + nt * 8 + q;
                b[nt][0] = Bu[(kk + t) * NP + nc];
                b[nt][1] = Bu[(kk + 4 + t) * NP + nc];
            }
#pragma unroll
            for (int mt = 0; mt < 2; mt++)
#pragma unroll
                for (int nt = 0; nt < NT; nt++) {
                    asm("mma.sync.aligned.m16n8k8.row.col.f32.tf32.tf32.f32 "
                        "{%0,%1,%2,%3}, {%4,%5,%6,%7}, {%8,%9}, {%0,%1,%2,%3};"
                        : "+f"(acc[mt][nt][0]), "+f"(acc[mt][nt][1]),
                          "+f"(acc[mt][nt][2]), "+f"(acc[mt][nt][3])
                        : "r"(a[mt][0]), "r"(a[mt][1]), "r"(a[mt][2]), "r"(a[mt][3]),
                          "r"(b[nt][0]), "r"(b[nt][1]));
                }
        }

        const int rowBase = tile * BM;
#pragma unroll
        for (int mt = 0; mt < 2; mt++) {
            int lr0 = warpM * 32 + mt * 16 + q;
            int r0 = rowBase + lr0;
            float p0 = 0.f, p1 = 0.f;
#pragma unroll
            for (int nt = 0; nt < NT; nt++) {
                int cb = warpN * WN + nt * 8 + t * 2;
                float v0 = acc[mt][nt][0], v1 = acc[mt][nt][1];
                float v2 = acc[mt][nt][2], v3 = acc[mt][nt][3];
                if (BIAS) {
                    v0 += bias[cb]; v1 += bias[cb + 1];
                    v2 += bias[cb]; v3 += bias[cb + 1];
                }
                float* Yt;
                const float* avt;
                int cc;
                if (N == 256) {
                    bool hi = cb >= 128;
                    Yt = hi ? Y1 : Y0;
                    avt = hi ? av1 : av0;
                    cc = cb & 127;
                } else {
                    Yt = Y0; avt = av0; cc = cb;
                }
                constexpr int YSTR = (N == 256) ? 128 : N;
                if (r0 < M) *(float2*)(Yt + (size_t)r0 * YSTR + cc) = make_float2(v0, v1);
                if (r0 + 8 < M) *(float2*)(Yt + (size_t)(r0 + 8) * YSTR + cc) = make_float2(v2, v3);
                if (ALPHA) {
                    float a0 = avt[cc], a1 = avt[cc + 1];
                    p0 += v0 * a0 + v1 * a1;
                    p1 += v2 * a0 + v3 * a1;
                }
            }
            if (ALPHA) {
                p0 += __shfl_xor_sync(0xffffffffu, p0, 1);
                p0 += __shfl_xor_sync(0xffffffffu, p0, 2);
                p1 += __shfl_xor_sync(0xffffffffu, p1, 1);
                p1 += __shfl_xor_sync(0xffffffffu, p1, 2);
                if (t == 0) {
                    red[lr0 * 5 + warpN] = p0;
                    red[(lr0 + 8) * 5 + warpN] = p1;
                }
            }
        }
        __syncthreads();
        if (ALPHA) {
            if (tid < BM) {
                int gr = rowBase + tid;
                if (gr < M) {
                    al0[gr] = red[tid * 5 + 0] + red[tid * 5 + 1];
                    al1[gr] = red[tid * 5 + 2] + red[tid * 5 + 3];
                }
            }
            __syncthreads();
        }
    }
}

// ---------------------------------------------------------------------------
// Aggregation: one warp per target node; att precomputed (coalesced loads).
// ---------------------------------------------------------------------------
__global__ __launch_bounds__(256)
void k_agg(const float4* __restrict__ tgt, const float4* __restrict__ src,
           const float* __restrict__ att,
           const int* __restrict__ off, const int* __restrict__ csr,
           float4* __restrict__ out, int n) {
    int w = (blockIdx.x * blockDim.x + threadIdx.x) >> 5;
    int lid = threadIdx.x & 31;
    if (w >= n) return;
    int beg = off[w];
    int end = off[w + 1];
    float4 acc = make_float4(0.f, 0.f, 0.f, 0.f);
    float den = 0.f;
    int j = beg;
    for (; j + 3 < end; j += 4) {
        int s0 = csr[j + 0], s1 = csr[j + 1], s2 = csr[j + 2], s3 = csr[j + 3];
        float a0 = att[j + 0], a1 = att[j + 1], a2 = att[j + 2], a3 = att[j + 3];
        float4 v0 = src[(size_t)s0 * 32 + lid];
        float4 v1 = src[(size_t)s1 * 32 + lid];
        float4 v2 = src[(size_t)s2 * 32 + lid];
        float4 v3 = src[(size_t)s3 * 32 + lid];
        den += (a0 + a1) + (a2 + a3);
        acc.x += a0 * v0.x + a1 * v1.x + a2 * v2.x + a3 * v3.x;
        acc.y += a0 * v0.y + a1 * v1.y + a2 * v2.y + a3 * v3.y;
        acc.z += a0 * v0.z + a1 * v1.z + a2 * v2.z + a3 * v3.z;
        acc.w += a0 * v0.w + a1 * v1.w + a2 * v2.w + a3 * v3.w;
    }
    if (j + 1 < end) {
        int s0 = csr[j + 0], s1 = csr[j + 1];
        float a0 = att[j + 0], a1 = att[j + 1];
        float4 v0 = src[(size_t)s0 * 32 + lid];
        float4 v1 = src[(size_t)s1 * 32 + lid];
        den += a0 + a1;
        acc.x += a0 * v0.x + a1 * v1.x;
        acc.y += a0 * v0.y + a1 * v1.y;
        acc.z += a0 * v0.z + a1 * v1.z;
        acc.w += a0 * v0.w + a1 * v1.w;
        j += 2;
    }
    if (j < end) {
        int s0 = csr[j];
        float a0 = att[j];
        float4 v0 = src[(size_t)s0 * 32 + lid];
        den += a0;
        acc.x += a0 * v0.x; acc.y += a0 * v0.y;
        acc.z += a0 * v0.z; acc.w += a0 * v0.w;
    }
    float inv = 1.0f / (den + EPSF);
    float4 tv = tgt[(size_t)w * 32 + lid];
    float4 r;
    r.x = fmaxf(tv.x + acc.x * inv, 0.f);
    r.y = fmaxf(tv.y + acc.y * inv, 0.f);
    r.z = fmaxf(tv.z + acc.z * inv, 0.f);
    r.w = fmaxf(tv.w + acc.w * inv, 0.f);
    out[(size_t)w * 32 + lid] = r;
}

// ---------------------------------------------------------------------------
// Host launcher
// ---------------------------------------------------------------------------
static inline float* symf(const void* sym) {
    void* p = nullptr;
    cudaGetSymbolAddress(&p, sym);
    return (float*)p;
}
static inline int* symi(const void* sym) {
    void* p = nullptr;
    cudaGetSymbolAddress(&p, sym);
    return (int*)p;
}

extern "C" void kernel_launch(void* const* d_in, const int* in_sizes, int n_in,
                              void* d_out, int out_size) {
    const float* x_user = (const float*)d_in[0];
    const float* x_spot = (const float*)d_in[1];
    const int*   e_us   = (const int*)d_in[2];
    const int*   e_su   = (const int*)d_in[3];
    const float* Ws_us0 = (const float*)d_in[4];
    const float* Wt_us0 = (const float*)d_in[5];
    const float* a_us0  = (const float*)d_in[6];
    const float* Ws_su0 = (const float*)d_in[7];
    const float* Wt_su0 = (const float*)d_in[8];
    const float* a_su0  = (const float*)d_in[9];
    const float* Ws_us1 = (const float*)d_in[10];
    const float* Wt_us1 = (const float*)d_in[11];
    const float* a_us1  = (const float*)d_in[12];
    const float* Ws_su1 = (const float*)d_in[13];
    const float* Wt_su1 = (const float*)d_in[14];
    const float* a_su1  = (const float*)d_in[15];
    const float* W_ou   = (const float*)d_in[16];
    const float* b_ou   = (const float*)d_in[17];
    const float* W_os   = (const float*)d_in[18];
    const float* b_os   = (const float*)d_in[19];

    float* out = (float*)d_out;
    float* xu_out = out;
    float* xs_out = out + (size_t)N_USER * HID;
    float* ou_out = xs_out + (size_t)N_SPOT * HID;
    float* os_out = ou_out + (size_t)N_USER * OUTC;

    float* srcA = symf(g_srcA); float* tgtA = symf(g_tgtA);
    float* srcB = symf(g_srcB); float* tgtB = symf(g_tgtB);
    float* hu = symf(g_hu);     float* hs = symf(g_hs);
    float* alsA = symf(g_alsA); float* altA = symf(g_altA);
    float* alsB = symf(g_alsB); float* altB = symf(g_altB);
    int* si2_us = symi(g_si2_us); int* si2_su = symi(g_si2_su);
    int* cnt_us = symi(g_cnt_us); int* off_us = symi(g_off_us); int* cur_us = symi(g_cur_us);
    int* cnt_su = symi(g_cnt_su); int* off_su = symi(g_off_su); int* cur_su = symi(g_cur_su);
    int* csr_us = symi(g_csr_us); int* csr_su = symi(g_csr_su);
    int* row_us = symi(g_row_us); int* row_su = symi(g_row_su);
    float* attb = symf(g_att);

    const int EB = (EDG + 255) / 256;
    const int GP = 296;                    // persistent grid, 2 CTAs/SM
    const int GP1 = 148;                   // L1 fused (170 KB smem -> 1 CTA/SM)
    const int AU = (N_USER * 32 + 255) / 256;
    const int AS = (N_SPOT * 32 + 255) / 256;

    const int SM_L0 = (64 * (256 + 8) + 64 * (64 + 4) + 64 * 5) * 4;     // ~86 KB
    const int SM_L1 = (128 * (256 + 8) + 64 * (128 + 4) + 64 * 5) * 4;   // ~170 KB
    const int SM_FN = (128 * (64 + 8) + 64 * (128 + 4) + 64 * 5) * 4;    // ~72 KB

    cudaFuncSetAttribute((const void*)k_gemm_tc<64, 256, true, false>,
                         cudaFuncAttributeMaxDynamicSharedMemorySize, SM_L0);
    cudaFuncSetAttribute((const void*)k_gemm_tc<128, 256, true, false>,
                         cudaFuncAttributeMaxDynamicSharedMemorySize, SM_L1);
    cudaFuncSetAttribute((const void*)k_gemm_tc<128, 64, false, true>,
                         cudaFuncAttributeMaxDynamicSharedMemorySize, SM_FN);

    // ---- prep; launch index 5 = fused L0 GEMM (profiled) ----
    k_gather2<<<EB, 256>>>(e_us, si2_us, EDG);                               // 0
    k_gather2<<<EB, 256>>>(e_su, si2_su, EDG);                               // 1
    cudaMemsetAsync(cnt_us, 0, sizeof(int) * (N_SPOT + 1));                  // 2
    cudaMemsetAsync(cnt_su, 0, sizeof(int) * (N_USER + 1));                  // 3
    k_hist<<<EB, 256>>>(e_us + EDG, cnt_us, EDG);                            // 4
    // x_user -> [srcA | tgtB], alphas [alsA | altB]
    k_gemm_tc<64, 256, true, false><<<GP, 256, SM_L0>>>(                     // 5
        x_user, Ws_us0, Wt_su0, a_us0, a_su0 + HID, nullptr,
        srcA, tgtB, alsA, altB, N_USER);
    k_hist<<<EB, 256>>>(e_su + EDG, cnt_su, EDG);
    k_scan<<<1, 1024>>>(cnt_us, off_us, cur_us, N_SPOT);
    k_scan<<<1, 1024>>>(cnt_su, off_su, cur_su, N_USER);
    k_scatter<<<EB, 256>>>(e_us + EDG, si2_us, cur_us, csr_us, row_us, EDG);
    k_scatter<<<EB, 256>>>(e_su + EDG, si2_su, cur_su, csr_su, row_su, EDG);
    // x_spot -> [srcB | tgtA], alphas [alsB | altA]
    k_gemm_tc<64, 256, true, false><<<GP, 256, SM_L0>>>(
        x_spot, Ws_su0, Wt_us0, a_su0, a_us0 + HID, nullptr,
        srcB, tgtA, alsB, altA, N_SPOT);

    // ---- layer 0 aggregation ----
    k_att<<<EB, 256>>>(csr_us, row_us, alsA, altA, attb, EDG);
    k_agg<<<AS, 256>>>((const float4*)tgtA, (const float4*)srcA, attb,
                       off_us, csr_us, (float4*)hs, N_SPOT);
    k_att<<<EB, 256>>>(csr_su, row_su, alsB, altB, attb, EDG);
    k_agg<<<AU, 256>>>((const float4*)tgtB, (const float4*)srcB, attb,
                       off_su, csr_su, (float4*)hu, N_USER);

    // ---- layer 1 (K=128, fused) ----
    k_gemm_tc<128, 256, true, false><<<GP1, 256, SM_L1>>>(
        hu, Ws_us1, Wt_su1, a_us1, a_su1 + HID, nullptr,
        srcA, tgtB, alsA, altB, N_USER);
    k_gemm_tc<128, 256, true, false><<<GP1, 256, SM_L1>>>(
        hs, Ws_su1, Wt_us1, a_su1, a_us1 + HID, nullptr,
        srcB, tgtA, alsB, altA, N_SPOT);
    k_att<<<EB, 256>>>(csr_us, row_us, alsA, altA, attb, EDG);
    k_agg<<<AS, 256>>>((const float4*)tgtA, (const float4*)srcA, attb,
                       off_us, csr_us, (float4*)xs_out, N_SPOT);
    k_att<<<EB, 256>>>(csr_su, row_su, alsB, altB, attb, EDG);
    k_agg<<<AU, 256>>>((const float4*)tgtB, (const float4*)srcB, attb,
                       off_su, csr_su, (float4*)xu_out, N_USER);

    // ---- final per-type linear (K=128, N=64, bias) ----
    k_gemm_tc<128, 64, false, true><<<GP, 256, SM_FN>>>(
        xu_out, W_ou, nullptr, nullptr, nullptr, b_ou,
        ou_out, nullptr, nullptr, nullptr, N_USER);
    k_gemm_tc<128, 64, false, true><<<GP, 256, SM_FN>>>(
        xs_out, W_os, nullptr, nullptr, nullptr, b_os,
        os_out, nullptr, nullptr, nullptr, N_SPOT);
}